// round 10
// baseline (speedup 1.0000x reference)
#include <cuda_runtime.h>
#include <cstdint>

#define B_ 128
#define K_ 65536
#define C_ 768
#define POSCAP 4096
#define FULLW 0xffffffffu
#define TILE 4096

// ---------------- device scratch ----------------
static __device__ unsigned g_keysA[(size_t)B_ * K_];
static __device__ unsigned g_keysB[(size_t)B_ * K_];
static __device__ float    g_cos[(size_t)B_ * K_];
static __device__ float    g_posv[B_ * POSCAP];
static __device__ unsigned g_qh[3][B_][4][256];
static __device__ int      g_neg_cnt[B_];
static __device__ int      g_pos_wr[B_];
static __device__ int      g_minpos;
static __device__ int      g_maxpos;
static __device__ int      g_pos_min;
static __device__ int      g_neg_min;
static __device__ int      g_reps;
static __device__ int      g_lstride;
static __device__ float    g_poscat[B_ * 32];

__device__ __forceinline__ unsigned flip_f32(float v) {
    unsigned b = __float_as_uint(v);
    return (b & 0x80000000u) ? ~b : (b | 0x80000000u);
}
__device__ __forceinline__ float unflip_f32(unsigned u) {
    unsigned b = (u & 0x80000000u) ? (u & 0x7fffffffu) : ~u;
    return __uint_as_float(b);
}

#define PACK2(dst, lo, hi) asm("mov.b64 %0, {%1, %2};" : "=l"(dst) : "f"(lo), "f"(hi))
#define FMA2(d, a, b)      asm("fma.rn.f32x2 %0, %1, %2, %0;" : "+l"(d) : "l"(a), "l"(b))

// ---------------- init ----------------
__global__ void k_init(const unsigned* __restrict__ lQ) {
    int b = blockIdx.x, t = threadIdx.x;
    if (t == 0) { g_neg_cnt[b] = 0; g_pos_wr[b] = 0; }
#pragma unroll
    for (int i = 0; i < 3; i++)
        for (int z = t; z < 1024; z += 256)
            g_qh[i][b][z >> 8][z & 255] = 0;
    if (b == 0) {
        if (t == 0) { g_minpos = 1 << 30; g_maxpos = 0; }
        unsigned v = 0;
        for (int i = 2 * t + 1; i < 16384; i += 512) v |= lQ[i];
        __shared__ unsigned sh[256];
        sh[t] = v; __syncthreads();
        for (int o = 128; o; o >>= 1) { if (t < o) sh[t] |= sh[t + o]; __syncthreads(); }
        if (t == 0) g_lstride = (sh[0] == 0u) ? 2 : 1;
    }
}

// ---------------- per-row positive counts ----------------
__global__ void k_count(const unsigned* __restrict__ lq, const unsigned* __restrict__ lQ) {
    int b = blockIdx.x, t = threadIdx.x, s = g_lstride;
    unsigned my = lq[b * s];
    int c = 0;
    for (int k = t; k < K_; k += 256) c += (lQ[(size_t)k * s] == my);
    __shared__ int sh[256];
    sh[t] = c; __syncthreads();
    for (int o = 128; o; o >>= 1) { if (t < o) sh[t] += sh[t + o]; __syncthreads(); }
    if (t == 0) { atomicMin(&g_minpos, sh[0]); atomicMax(&g_maxpos, sh[0]); }
}

__global__ void k_fin(const int* __restrict__ tkp) {
    int tk = *tkp;
    g_pos_min = g_minpos;
    g_neg_min = K_ - g_maxpos;
    int t = (tk < g_minpos) ? tk : g_minpos;
    g_reps = t + 1;
}

// ---------------- fp32 GEMM (f32x2 FMA, dup-A smem, XOR swizzle) ----------------
#define KC 32
__global__ __launch_bounds__(256, 2) void k_gemm(const float* __restrict__ A,
                                                 const float* __restrict__ Bq) {
    __shared__ float As[KC * 256];   // dup: slot s -> (a_s, a_s) at floats 2s, 2s+1
    __shared__ float Bs[KC * 128];
    int t  = threadIdx.x;
    int nt = blockIdx.x * 128;
    int tx = t & 15, ty = t >> 4;
    int lr = t >> 3, lk4 = (t & 7) * 4;

    unsigned long long acc[8][4];
#pragma unroll
    for (int i = 0; i < 8; i++)
#pragma unroll
        for (int j = 0; j < 4; j++) acc[i][j] = 0ull;

    for (int k0 = 0; k0 < C_; k0 += KC) {
#pragma unroll
        for (int it = 0; it < 4; it++) {
            int r = it * 32 + lr;
            int rs = r ^ lk4;   // XOR swizzle on the 128-row dim
            float4 av = *(const float4*)&A[r * C_ + k0 + lk4];
            float4 bv = *(const float4*)&Bq[(size_t)(nt + r) * C_ + k0 + lk4];
            *(float2*)&As[(lk4 + 0) * 256 + rs * 2] = make_float2(av.x, av.x);
            *(float2*)&As[(lk4 + 1) * 256 + rs * 2] = make_float2(av.y, av.y);
            *(float2*)&As[(lk4 + 2) * 256 + rs * 2] = make_float2(av.z, av.z);
            *(float2*)&As[(lk4 + 3) * 256 + rs * 2] = make_float2(av.w, av.w);
            Bs[(lk4 + 0) * 128 + rs] = bv.x; Bs[(lk4 + 1) * 128 + rs] = bv.y;
            Bs[(lk4 + 2) * 128 + rs] = bv.z; Bs[(lk4 + 3) * 128 + rs] = bv.w;
        }
        __syncthreads();
#pragma unroll
        for (int k = 0; k < KC; k++) {
            int fa = k & 28;
            const float* adrow = &As[k * 256];
            const float* brow  = &Bs[k * 128];
            int bA = (ty * 8) ^ fa;
            int bB = (tx * 8) ^ fa;
            float4 ad0 = *(const float4*)&adrow[bA * 2];        // rows 0,1 dup-pairs
            float4 ad1 = *(const float4*)&adrow[bA * 2 + 4];    // rows 2,3
            float4 ad2 = *(const float4*)&adrow[(bA ^ 4) * 2];  // rows 4,5
            float4 ad3 = *(const float4*)&adrow[(bA ^ 4) * 2 + 4]; // rows 6,7
            float4 b0 = *(const float4*)&brow[bB];
            float4 b1 = *(const float4*)&brow[bB ^ 4];
            unsigned long long bp0, bp1, bp2, bp3;
            PACK2(bp0, b0.x, b0.y); PACK2(bp1, b0.z, b0.w);
            PACK2(bp2, b1.x, b1.y); PACK2(bp3, b1.z, b1.w);
            unsigned long long ap[8];
            PACK2(ap[0], ad0.x, ad0.y); PACK2(ap[1], ad0.z, ad0.w);
            PACK2(ap[2], ad1.x, ad1.y); PACK2(ap[3], ad1.z, ad1.w);
            PACK2(ap[4], ad2.x, ad2.y); PACK2(ap[5], ad2.z, ad2.w);
            PACK2(ap[6], ad3.x, ad3.y); PACK2(ap[7], ad3.z, ad3.w);
#pragma unroll
            for (int i = 0; i < 8; i++) {
                FMA2(acc[i][0], ap[i], bp0);
                FMA2(acc[i][1], ap[i], bp1);
                FMA2(acc[i][2], ap[i], bp2);
                FMA2(acc[i][3], ap[i], bp3);
            }
        }
        __syncthreads();
    }
#pragma unroll
    for (int i = 0; i < 8; i++) {
        int row = ty * 8 + i;
        unsigned long long* d = (unsigned long long*)&g_cos[(size_t)row * K_ + nt + tx * 8];
        d[0] = acc[i][0]; d[1] = acc[i][1]; d[2] = acc[i][2]; d[3] = acc[i][3];
    }
}

// ---------------- partition + pass-1 per-quarter histogram ----------------
__global__ __launch_bounds__(256) void k_part(const unsigned* __restrict__ lq,
                                              const unsigned* __restrict__ lQ) {
    __shared__ unsigned qh[1024];   // [quarter][digit] for pass-1 (bits 8-16)
    int row = blockIdx.x >> 3;
    int chunk = blockIdx.x & 7;
    int t = threadIdx.x, lane = t & 31;
    unsigned ltm = (1u << lane) - 1u;
    int s = g_lstride;
    unsigned myl = lq[row * s];
    for (int z = t; z < 1024; z += 256) qh[z] = 0;
    __syncthreads();
    const float* cosr = g_cos + (size_t)row * K_ + chunk * 8192;
    for (int q = 0; q < 32; q++) {
        int col = chunk * 8192 + q * 256 + t;
        float v = cosr[q * 256 + t];
        bool isPos = (lQ[(size_t)col * s] == myl);
        unsigned negm = __ballot_sync(FULLW, !isPos);
        if (!isPos) {
            int r = __popc(negm & ltm);
            int base = 0;
            if (r == 0) base = atomicAdd(&g_neg_cnt[row], __popc(negm));
            base = __shfl_sync(negm, base, __ffs(negm) - 1);
            unsigned u = flip_f32(v);
            int pos = base + r;
            g_keysA[((size_t)row << 16) + pos] = u;
            atomicAdd(&qh[((pos >> 14) << 8) | ((u >> 8) & 255u)], 1u);
        } else {
            unsigned posm = ~negm;
            int r = __popc(posm & ltm);
            int base = 0;
            if (r == 0) base = atomicAdd(&g_pos_wr[row], __popc(posm));
            base = __shfl_sync(posm, base, __ffs(posm) - 1);
            if (base + r < POSCAP) g_posv[row * POSCAP + base + r] = v;
        }
    }
    __syncthreads();
    for (int z = t; z < 1024; z += 256) {
        unsigned c = qh[z];
        if (c) atomicAdd(&g_qh[0][row][z >> 8][z & 255], c);
    }
}

// ---------------- one stable radix pass: CTA = (row, quarter), 4 tiles ----------------
__global__ __launch_bounds__(1024) void k_pass(int srcSel, int shift, int inIdx,
                                               int outIdx, int doNext) {
    int b = blockIdx.x >> 2, q = blockIdx.x & 3;
    int t = threadIdx.x, lane = t & 31, w = t >> 5;
    unsigned ltm = (1u << lane) - 1u;
    int n = g_neg_cnt[b];
    const unsigned* src = (srcSel ? g_keysB : g_keysA) + ((size_t)b << 16);
    unsigned*       dst = (srcSel ? g_keysA : g_keysB) + ((size_t)b << 16);
    int i0 = q << 14, i1 = i0 + 16384;
    if (i1 > n) i1 = n;
    if (i1 < i0) i1 = i0;
    int nextShift = shift + 8;

    __shared__ unsigned binbase[256];
    __shared__ unsigned tstart[256];
    __shared__ unsigned tiletot[256];
    __shared__ unsigned nh[1024];
    __shared__ __align__(16) unsigned short whist[8484];
    __shared__ __align__(16) unsigned skey[TILE];

    if (t < 1024) nh[t] = 0;
    if (w == 0) {   // global base + quarter prefix per digit
        unsigned vloc[8], pref[8], tot = 0;
#pragma unroll
        for (int c = 0; c < 8; c++) {
            int d = lane * 8 + c;
            unsigned s0 = g_qh[inIdx][b][0][d], s1 = g_qh[inIdx][b][1][d];
            unsigned s2 = g_qh[inIdx][b][2][d], s3 = g_qh[inIdx][b][3][d];
            pref[c] = (q > 0 ? s0 : 0u) + (q > 1 ? s1 : 0u) + (q > 2 ? s2 : 0u);
            unsigned td = s0 + s1 + s2 + s3;
            vloc[c] = tot; tot += td;
        }
        unsigned e = tot;
#pragma unroll
        for (int o = 1; o < 32; o <<= 1) { unsigned y = __shfl_up_sync(FULLW, e, o); if (lane >= o) e += y; }
        e -= tot;
#pragma unroll
        for (int c = 0; c < 8; c++) binbase[lane * 8 + c] = e + vloc[c] + pref[c];
    }
    __syncthreads();

    for (int tt = 0; tt < 4; tt++) {
        int base = i0 + tt * 4096;
        int tn = i1 - base;
        if (tn < 0) tn = 0;
        if (tn > TILE) tn = TILE;

        for (int z = t; z < 4242; z += 1024) ((unsigned*)whist)[z] = 0;
        __syncthreads();

        unsigned key[4], lr[4]; int dg[4];
#pragma unroll
        for (int qq = 0; qq < 4; qq++) {
            int idx = base + w * 128 + qq * 32 + lane;
            unsigned d = 256u;
            if (idx < i1) { key[qq] = src[idx]; d = (key[qq] >> shift) & 255u; }
            dg[qq] = (int)d;
            unsigned m = __match_any_sync(FULLW, d);
            unsigned r = __popc(m & ltm);
            int leader = __ffs(m) - 1;
            unsigned old = 0;
            if (r == 0) {
                old = whist[d * 33 + w];
                whist[d * 33 + w] = (unsigned short)(old + __popc(m));
            }
            old = __shfl_sync(m, old, leader);
            lr[qq] = old + r;
            __syncwarp();
        }
        __syncthreads();

        {   // column scan across 32 warps
            int bd = w * 8;
            unsigned v[8], o8[8];
#pragma unroll
            for (int c = 0; c < 8; c++) { v[c] = whist[(bd + c) * 33 + lane]; o8[c] = v[c]; }
#pragma unroll
            for (int o = 1; o < 32; o <<= 1) {
#pragma unroll
                for (int c = 0; c < 8; c++) {
                    unsigned y = __shfl_up_sync(FULLW, v[c], o);
                    if (lane >= o) v[c] += y;
                }
            }
#pragma unroll
            for (int c = 0; c < 8; c++) {
                whist[(bd + c) * 33 + lane] = (unsigned short)(v[c] - o8[c]);
                if (lane == 31) tiletot[bd + c] = v[c];
            }
        }
        __syncthreads();

        if (w == 0) {   // tile-local digit starts
            unsigned vloc[8], tot = 0;
#pragma unroll
            for (int c = 0; c < 8; c++) { unsigned x = tiletot[lane * 8 + c]; vloc[c] = tot; tot += x; }
            unsigned e = tot;
#pragma unroll
            for (int o = 1; o < 32; o <<= 1) { unsigned y = __shfl_up_sync(FULLW, e, o); if (lane >= o) e += y; }
            e -= tot;
#pragma unroll
            for (int c = 0; c < 8; c++) tstart[lane * 8 + c] = e + vloc[c];
        }
        __syncthreads();

#pragma unroll
        for (int qq = 0; qq < 4; qq++) {   // stage digit-contiguous in smem
            if (dg[qq] < 256) {
                unsigned p = tstart[dg[qq]] + (unsigned)whist[dg[qq] * 33 + w] + lr[qq];
                skey[p] = key[qq];
            }
        }
        __syncthreads();

        {   // coalesced scatter + next-pass histogram
            uint4 kk = *(const uint4*)&skey[t * 4];
            unsigned ks[4] = {kk.x, kk.y, kk.z, kk.w};
            int j0 = t * 4;
#pragma unroll
            for (int qq = 0; qq < 4; qq++) {
                int j = j0 + qq;
                if (j < tn) {
                    unsigned kq = ks[qq];
                    unsigned d = (kq >> shift) & 255u;
                    unsigned dp = binbase[d] + (unsigned)j - tstart[d];
                    dst[dp] = kq;
                    if (doNext)
                        atomicAdd(&nh[((dp >> 14) << 8) | ((kq >> nextShift) & 255u)], 1u);
                }
            }
        }
        __syncthreads();
        if (t < 256) binbase[t] += tiletot[t];
        __syncthreads();
    }
    if (doNext && t < 1024) {
        unsigned c = nh[t];
        if (c) atomicAdd(&g_qh[outIdx][b][t >> 8][t & 255], c);
    }
}

// ---------------- positives: smem bitonic sort (4096), emit pos_cat ----------------
__global__ __launch_bounds__(512) void k_possort() {
    __shared__ float s[4096];
    int b = blockIdx.x, t = threadIdx.x;
    int n = g_pos_wr[b];
    if (n > POSCAP) n = POSCAP;
    float ninf = __int_as_float(0xff800000);
    for (int i = t; i < 4096; i += 512)
        s[i] = (i < n) ? g_posv[b * POSCAP + i] : ninf;
    __syncthreads();
    for (int kk = 2; kk <= 4096; kk <<= 1) {
        for (int j = kk >> 1; j > 0; j >>= 1) {
            for (int i = t; i < 4096; i += 512) {
                int l = i ^ j;
                if (l > i) {
                    float a = s[i], c = s[l];
                    bool up = ((i & kk) == 0);
                    if (up ? (a > c) : (a < c)) { s[i] = c; s[l] = a; }
                }
            }
            __syncthreads();
        }
    }
    if (t == 0) {
        int tk = g_reps - 1;
        for (int j = 0; j < tk; j++) g_poscat[b * 32 + j] = s[4095 - j];
        g_poscat[b * 32 + tk] = s[4095 - (g_pos_min - 1)];
    }
}

// ---------------- writer: smem-broadcast, 8 segment-CTAs per b-row ----------------
__global__ __launch_bounds__(512) void k_write(float* __restrict__ out) {
    __shared__ __align__(16) float s[4096];
    int b = blockIdx.x >> 3;
    int seg = blockIdx.x & 7;
    int t = threadIdx.x;
    int reps = g_reps, nm = g_neg_min, cnt = g_neg_cnt[b];
    size_t W = (size_t)nm + 1;
    const unsigned* asc = g_keysB + ((size_t)b << 16);
    const float invT = 1.0f / 0.3f;

    if (seg == 0 && t < reps)
        out[(size_t)(b * reps + t) * W] = g_poscat[b * 32 + t] * invT;

    int per = (nm + 7) >> 3;
    int i0 = seg * per;
    int i1 = i0 + per; if (i1 > nm) i1 = nm;

    for (int c0 = i0; c0 < i1; c0 += 4096) {
        int len = i1 - c0; if (len > 4096) len = 4096;
        int glo = cnt - c0 - len;
        for (int u = t; u < len; u += 512)
            s[len - 1 - u] = unflip_f32(asc[glo + u]) * invT;
        __syncthreads();
        for (int j = 0; j < reps; j++) {
            size_t doff = (size_t)(b * reps + j) * W + 1 + c0;
            float* dst = out + doff;
            int head = (int)((4 - (doff & 3)) & 3); if (head > len) head = len;
            for (int u = t; u < head; u += 512) dst[u] = s[u];
            int nb = (len - head) >> 2;
            for (int u = t; u < nb; u += 512) {
                int p = head + u * 4;
                float4 v; v.x = s[p]; v.y = s[p + 1]; v.z = s[p + 2]; v.w = s[p + 3];
                __stcs((float4*)&dst[p], v);
            }
            for (int u = head + nb * 4 + t; u < len; u += 512) dst[u] = s[u];
        }
        __syncthreads();
    }
}

// ---------------- launch ----------------
extern "C" void kernel_launch(void* const* d_in, const int* in_sizes, int n_in,
                              void* d_out, int out_size) {
    const float*    A  = (const float*)d_in[0];
    const float*    Bq = (const float*)d_in[1];
    const unsigned* lq = (const unsigned*)d_in[2];
    const unsigned* lQ = (const unsigned*)d_in[3];
    const int*      tk = (const int*)d_in[4];
    float* out = (float*)d_out;
    (void)in_sizes; (void)n_in; (void)out_size;

    k_init<<<B_, 256>>>(lQ);
    k_count<<<B_, 256>>>(lq, lQ);
    k_fin<<<1, 1>>>(tk);
    k_gemm<<<K_ / 128, 256>>>(A, Bq);
    k_part<<<B_ * 8, 256>>>(lq, lQ);
    k_pass<<<B_ * 4, 1024>>>(0, 8,  0, 1, 1);
    k_pass<<<B_ * 4, 1024>>>(1, 16, 1, 2, 1);
    k_pass<<<B_ * 4, 1024>>>(0, 24, 2, 2, 0);
    k_possort<<<B_, 512>>>();
    k_write<<<B_ * 8, 512>>>(out);
}

// round 11
// speedup vs baseline: 1.1213x; 1.1213x over previous
#include <cuda_runtime.h>
#include <cstdint>

#define B_ 128
#define K_ 65536
#define C_ 768
#define POSCAP 4096
#define FULLW 0xffffffffu
#define TILE 4096

// ---------------- device scratch ----------------
static __device__ unsigned g_keysA[(size_t)B_ * K_];
static __device__ unsigned g_keysB[(size_t)B_ * K_];
static __device__ float    g_cos[(size_t)B_ * K_];
static __device__ float    g_posv[B_ * POSCAP];
static __device__ unsigned g_qh[3][B_][4][256];
static __device__ int      g_neg_cnt[B_];
static __device__ int      g_pos_wr[B_];
static __device__ int      g_minpos;
static __device__ int      g_maxpos;
static __device__ int      g_pos_min;
static __device__ int      g_neg_min;
static __device__ int      g_reps;
static __device__ int      g_lstride;
static __device__ float    g_poscat[B_ * 32];
static __device__ __align__(16) unsigned char g_lab8[K_];
static __device__ unsigned char g_labq8[B_];

__device__ __forceinline__ unsigned flip_f32(float v) {
    unsigned b = __float_as_uint(v);
    return (b & 0x80000000u) ? ~b : (b | 0x80000000u);
}
__device__ __forceinline__ float unflip_f32(unsigned u) {
    unsigned b = (u & 0x80000000u) ? (u & 0x7fffffffu) : ~u;
    return __uint_as_float(b);
}

#define PACK2(dst, lo, hi) asm("mov.b64 %0, {%1, %2};" : "=l"(dst) : "f"(lo), "f"(hi))
#define FMA2(d, a, b)      asm("fma.rn.f32x2 %0, %1, %2, %0;" : "+l"(d) : "l"(a), "l"(b))

// ---------------- init ----------------
__global__ void k_init(const unsigned* __restrict__ lQ) {
    int b = blockIdx.x, t = threadIdx.x;
    if (t == 0) { g_neg_cnt[b] = 0; g_pos_wr[b] = 0; }
#pragma unroll
    for (int i = 0; i < 3; i++)
        for (int z = t; z < 1024; z += 256)
            g_qh[i][b][z >> 8][z & 255] = 0;
    if (b == 0) {
        if (t == 0) { g_minpos = 1 << 30; g_maxpos = 0; }
        unsigned v = 0;
        for (int i = 2 * t + 1; i < 16384; i += 512) v |= lQ[i];
        __shared__ unsigned sh[256];
        sh[t] = v; __syncthreads();
        for (int o = 128; o; o >>= 1) { if (t < o) sh[t] |= sh[t + o]; __syncthreads(); }
        if (t == 0) g_lstride = (sh[0] == 0u) ? 2 : 1;
    }
}

// ---------------- compress labels to u8 ----------------
__global__ void k_lab(const unsigned* __restrict__ lq, const unsigned* __restrict__ lQ) {
    int s = g_lstride;
    int i = (blockIdx.x * 256 + threadIdx.x) * 4;
    uchar4 v;
    v.x = (unsigned char)lQ[(size_t)(i + 0) * s];
    v.y = (unsigned char)lQ[(size_t)(i + 1) * s];
    v.z = (unsigned char)lQ[(size_t)(i + 2) * s];
    v.w = (unsigned char)lQ[(size_t)(i + 3) * s];
    *(uchar4*)&g_lab8[i] = v;
    if (blockIdx.x == 0 && threadIdx.x < B_)
        g_labq8[threadIdx.x] = (unsigned char)lq[threadIdx.x * s];
}

// ---------------- per-row positive counts (u8 labels) ----------------
__global__ void k_count() {
    int b = blockIdx.x, t = threadIdx.x;
    unsigned mx = g_labq8[b] * 0x01010101u;
    int c8 = 0;
    const uint4* L = (const uint4*)g_lab8;
    for (int k = t; k < K_ / 16; k += 256) {
        uint4 w = L[k];
        c8 += __popc(__vcmpeq4(w.x, mx)) + __popc(__vcmpeq4(w.y, mx))
            + __popc(__vcmpeq4(w.z, mx)) + __popc(__vcmpeq4(w.w, mx));
    }
    int c = c8 >> 3;
    __shared__ int sh[256];
    sh[t] = c; __syncthreads();
    for (int o = 128; o; o >>= 1) { if (t < o) sh[t] += sh[t + o]; __syncthreads(); }
    if (t == 0) { atomicMin(&g_minpos, sh[0]); atomicMax(&g_maxpos, sh[0]); }
}

__global__ void k_fin(const int* __restrict__ tkp) {
    int tk = *tkp;
    g_pos_min = g_minpos;
    g_neg_min = K_ - g_maxpos;
    int t = (tk < g_minpos) ? tk : g_minpos;
    g_reps = t + 1;
}

// ---------------- fp32 GEMM (f32x2 FMA, XOR-swizzled smem) — R9 proven ----------------
#define KC 32
__global__ __launch_bounds__(256, 2) void k_gemm(const float* __restrict__ A,
                                                 const float* __restrict__ Bq) {
    __shared__ float As[KC * 128];
    __shared__ float Bs[KC * 128];
    int t  = threadIdx.x;
    int nt = blockIdx.x * 128;
    int tx = t & 15, ty = t >> 4;
    int lr = t >> 3, lk4 = (t & 7) * 4;

    unsigned long long acc[8][4];
#pragma unroll
    for (int i = 0; i < 8; i++)
#pragma unroll
        for (int j = 0; j < 4; j++) acc[i][j] = 0ull;

    for (int k0 = 0; k0 < C_; k0 += KC) {
#pragma unroll
        for (int it = 0; it < 4; it++) {
            int r = it * 32 + lr;
            int rs = r ^ lk4;
            float4 av = *(const float4*)&A[r * C_ + k0 + lk4];
            float4 bv = *(const float4*)&Bq[(size_t)(nt + r) * C_ + k0 + lk4];
            As[(lk4 + 0) * 128 + rs] = av.x; As[(lk4 + 1) * 128 + rs] = av.y;
            As[(lk4 + 2) * 128 + rs] = av.z; As[(lk4 + 3) * 128 + rs] = av.w;
            Bs[(lk4 + 0) * 128 + rs] = bv.x; Bs[(lk4 + 1) * 128 + rs] = bv.y;
            Bs[(lk4 + 2) * 128 + rs] = bv.z; Bs[(lk4 + 3) * 128 + rs] = bv.w;
        }
        __syncthreads();
#pragma unroll
        for (int k = 0; k < KC; k++) {
            int fa = k & 28;
            const float* arow = &As[k * 128];
            const float* brow = &Bs[k * 128];
            int bA = (ty * 8) ^ fa;
            int bB = (tx * 8) ^ fa;
            float4 a0 = *(const float4*)&arow[bA];
            float4 a1 = *(const float4*)&arow[bA ^ 4];
            float4 b0 = *(const float4*)&brow[bB];
            float4 b1 = *(const float4*)&brow[bB ^ 4];
            unsigned long long bp0, bp1, bp2, bp3;
            PACK2(bp0, b0.x, b0.y); PACK2(bp1, b0.z, b0.w);
            PACK2(bp2, b1.x, b1.y); PACK2(bp3, b1.z, b1.w);
            float aa[8] = {a0.x, a0.y, a0.z, a0.w, a1.x, a1.y, a1.z, a1.w};
#pragma unroll
            for (int i = 0; i < 8; i++) {
                unsigned long long ap; PACK2(ap, aa[i], aa[i]);
                FMA2(acc[i][0], ap, bp0);
                FMA2(acc[i][1], ap, bp1);
                FMA2(acc[i][2], ap, bp2);
                FMA2(acc[i][3], ap, bp3);
            }
        }
        __syncthreads();
    }
#pragma unroll
    for (int i = 0; i < 8; i++) {
        int row = ty * 8 + i;
        unsigned long long* d = (unsigned long long*)&g_cos[(size_t)row * K_ + nt + tx * 8];
        d[0] = acc[i][0]; d[1] = acc[i][1]; d[2] = acc[i][2]; d[3] = acc[i][3];
    }
}

// ---------------- partition (4 elems/thread, u8 labels) + pass-1 quarter hist ----------------
__global__ __launch_bounds__(256) void k_part() {
    __shared__ unsigned qh[1024];   // [quarter][digit] for pass-1 (bits 8-16)
    int row = blockIdx.x >> 3;
    int chunk = blockIdx.x & 7;
    int t = threadIdx.x, lane = t & 31;
    unsigned ltm = (1u << lane) - 1u;
    unsigned mylx4 = g_labq8[row] * 0x01010101u;
    for (int z = t; z < 1024; z += 256) qh[z] = 0;
    __syncthreads();
    const float4* cosr = (const float4*)(g_cos + (size_t)row * K_) + chunk * 2048;
    const unsigned* lab4 = (const unsigned*)g_lab8 + chunk * 2048;
    unsigned* keys = g_keysA + ((size_t)row << 16);

    for (int it = 0; it < 8; it++) {
        float4 v = cosr[it * 256 + t];
        unsigned lb = lab4[it * 256 + t];
        unsigned eq = __vcmpeq4(lb, mylx4);
        unsigned m[4];
        m[0] = __ballot_sync(FULLW, (eq & 0x000000FFu) == 0);
        m[1] = __ballot_sync(FULLW, (eq & 0x0000FF00u) == 0);
        m[2] = __ballot_sync(FULLW, (eq & 0x00FF0000u) == 0);
        m[3] = __ballot_sync(FULLW, (eq & 0xFF000000u) == 0);
        int c0 = __popc(m[0]), c1 = __popc(m[1]), c2 = __popc(m[2]), c3 = __popc(m[3]);
        int tot = c0 + c1 + c2 + c3;
        int nbase = 0, pbase = 0;
        if (lane == 0) {
            if (tot) nbase = atomicAdd(&g_neg_cnt[row], tot);
            if (tot < 128) pbase = atomicAdd(&g_pos_wr[row], 128 - tot);
        }
        nbase = __shfl_sync(FULLW, nbase, 0);
        pbase = __shfl_sync(FULLW, pbase, 0);
        int npre[4] = {0, c0, c0 + c1, c0 + c1 + c2};
        float vals[4] = {v.x, v.y, v.z, v.w};
#pragma unroll
        for (int e = 0; e < 4; e++) {
            bool neg = (m[e] >> lane) & 1;
            if (neg) {
                int idx = nbase + npre[e] + __popc(m[e] & ltm);
                unsigned u = flip_f32(vals[e]);
                keys[idx] = u;
                atomicAdd(&qh[((idx >> 14) << 8) | ((u >> 8) & 255u)], 1u);
            } else {
                int pidx = pbase + (32 * e - npre[e]) + __popc(~m[e] & ltm);
                if (pidx < POSCAP) g_posv[row * POSCAP + pidx] = vals[e];
            }
        }
    }
    __syncthreads();
    for (int z = t; z < 1024; z += 256) {
        unsigned c = qh[z];
        if (c) atomicAdd(&g_qh[0][row][z >> 8][z & 255], c);
    }
}

// ---------------- one stable radix pass: CTA = (row, quarter), 4 tiles ----------------
__global__ __launch_bounds__(1024) void k_pass(int srcSel, int shift, int inIdx,
                                               int outIdx, int doNext) {
    int b = blockIdx.x >> 2, q = blockIdx.x & 3;
    int t = threadIdx.x, lane = t & 31, w = t >> 5;
    unsigned ltm = (1u << lane) - 1u;
    int n = g_neg_cnt[b];
    const unsigned* src = (srcSel ? g_keysB : g_keysA) + ((size_t)b << 16);
    unsigned*       dst = (srcSel ? g_keysA : g_keysB) + ((size_t)b << 16);
    int i0 = q << 14, i1 = i0 + 16384;
    if (i1 > n) i1 = n;
    if (i1 < i0) i1 = i0;
    int nextShift = shift + 8;

    __shared__ unsigned binbase[256];
    __shared__ unsigned tstart[256];
    __shared__ unsigned tiletot[256];
    __shared__ unsigned nh[1024];
    __shared__ __align__(16) unsigned short whist[8484];
    __shared__ __align__(16) unsigned skey[TILE];

    if (t < 1024) nh[t] = 0;
    if (w == 0) {
        unsigned vloc[8], pref[8], tot = 0;
#pragma unroll
        for (int c = 0; c < 8; c++) {
            int d = lane * 8 + c;
            unsigned s0 = g_qh[inIdx][b][0][d], s1 = g_qh[inIdx][b][1][d];
            unsigned s2 = g_qh[inIdx][b][2][d], s3 = g_qh[inIdx][b][3][d];
            pref[c] = (q > 0 ? s0 : 0u) + (q > 1 ? s1 : 0u) + (q > 2 ? s2 : 0u);
            unsigned td = s0 + s1 + s2 + s3;
            vloc[c] = tot; tot += td;
        }
        unsigned e = tot;
#pragma unroll
        for (int o = 1; o < 32; o <<= 1) { unsigned y = __shfl_up_sync(FULLW, e, o); if (lane >= o) e += y; }
        e -= tot;
#pragma unroll
        for (int c = 0; c < 8; c++) binbase[lane * 8 + c] = e + vloc[c] + pref[c];
    }
    __syncthreads();

    for (int tt = 0; tt < 4; tt++) {
        int base = i0 + tt * 4096;
        int tn = i1 - base;
        if (tn < 0) tn = 0;
        if (tn > TILE) tn = TILE;

        for (int z = t; z < 4242; z += 1024) ((unsigned*)whist)[z] = 0;
        __syncthreads();

        unsigned key[4], lr[4]; int dg[4];
#pragma unroll
        for (int qq = 0; qq < 4; qq++) {
            int idx = base + w * 128 + qq * 32 + lane;
            unsigned d = 256u;
            if (idx < i1) { key[qq] = src[idx]; d = (key[qq] >> shift) & 255u; }
            dg[qq] = (int)d;
            unsigned m = __match_any_sync(FULLW, d);
            unsigned r = __popc(m & ltm);
            int leader = __ffs(m) - 1;
            unsigned old = 0;
            if (r == 0) {
                old = whist[d * 33 + w];
                whist[d * 33 + w] = (unsigned short)(old + __popc(m));
            }
            old = __shfl_sync(m, old, leader);
            lr[qq] = old + r;
            __syncwarp();
        }
        __syncthreads();

        {
            int bd = w * 8;
            unsigned v[8], o8[8];
#pragma unroll
            for (int c = 0; c < 8; c++) { v[c] = whist[(bd + c) * 33 + lane]; o8[c] = v[c]; }
#pragma unroll
            for (int o = 1; o < 32; o <<= 1) {
#pragma unroll
                for (int c = 0; c < 8; c++) {
                    unsigned y = __shfl_up_sync(FULLW, v[c], o);
                    if (lane >= o) v[c] += y;
                }
            }
#pragma unroll
            for (int c = 0; c < 8; c++) {
                whist[(bd + c) * 33 + lane] = (unsigned short)(v[c] - o8[c]);
                if (lane == 31) tiletot[bd + c] = v[c];
            }
        }
        __syncthreads();

        if (w == 0) {
            unsigned vloc[8], tot = 0;
#pragma unroll
            for (int c = 0; c < 8; c++) { unsigned x = tiletot[lane * 8 + c]; vloc[c] = tot; tot += x; }
            unsigned e = tot;
#pragma unroll
            for (int o = 1; o < 32; o <<= 1) { unsigned y = __shfl_up_sync(FULLW, e, o); if (lane >= o) e += y; }
            e -= tot;
#pragma unroll
            for (int c = 0; c < 8; c++) tstart[lane * 8 + c] = e + vloc[c];
        }
        __syncthreads();

#pragma unroll
        for (int qq = 0; qq < 4; qq++) {
            if (dg[qq] < 256) {
                unsigned p = tstart[dg[qq]] + (unsigned)whist[dg[qq] * 33 + w] + lr[qq];
                skey[p] = key[qq];
            }
        }
        __syncthreads();

        {
            uint4 kk = *(const uint4*)&skey[t * 4];
            unsigned ks[4] = {kk.x, kk.y, kk.z, kk.w};
            int j0 = t * 4;
#pragma unroll
            for (int qq = 0; qq < 4; qq++) {
                int j = j0 + qq;
                if (j < tn) {
                    unsigned kq = ks[qq];
                    unsigned d = (kq >> shift) & 255u;
                    unsigned dp = binbase[d] + (unsigned)j - tstart[d];
                    dst[dp] = kq;
                    if (doNext)
                        atomicAdd(&nh[((dp >> 14) << 8) | ((kq >> nextShift) & 255u)], 1u);
                }
            }
        }
        __syncthreads();
        if (t < 256) binbase[t] += tiletot[t];
        __syncthreads();
    }
    if (doNext && t < 1024) {
        unsigned c = nh[t];
        if (c) atomicAdd(&g_qh[outIdx][b][t >> 8][t & 255], c);
    }
}

// ---------------- positives: smem bitonic sort (4096), emit pos_cat ----------------
__global__ __launch_bounds__(512) void k_possort() {
    __shared__ float s[4096];
    int b = blockIdx.x, t = threadIdx.x;
    int n = g_pos_wr[b];
    if (n > POSCAP) n = POSCAP;
    float ninf = __int_as_float(0xff800000);
    for (int i = t; i < 4096; i += 512)
        s[i] = (i < n) ? g_posv[b * POSCAP + i] : ninf;
    __syncthreads();
    for (int kk = 2; kk <= 4096; kk <<= 1) {
        for (int j = kk >> 1; j > 0; j >>= 1) {
            for (int i = t; i < 4096; i += 512) {
                int l = i ^ j;
                if (l > i) {
                    float a = s[i], c = s[l];
                    bool up = ((i & kk) == 0);
                    if (up ? (a > c) : (a < c)) { s[i] = c; s[l] = a; }
                }
            }
            __syncthreads();
        }
    }
    if (t == 0) {
        int tk = g_reps - 1;
        for (int j = 0; j < tk; j++) g_poscat[b * 32 + j] = s[4095 - j];
        g_poscat[b * 32 + tk] = s[4095 - (g_pos_min - 1)];
    }
}

// ---------------- writer: smem-broadcast, 8 segment-CTAs per b-row ----------------
__global__ __launch_bounds__(512) void k_write(float* __restrict__ out) {
    __shared__ __align__(16) float s[4096];
    int b = blockIdx.x >> 3;
    int seg = blockIdx.x & 7;
    int t = threadIdx.x;
    int reps = g_reps, nm = g_neg_min, cnt = g_neg_cnt[b];
    size_t W = (size_t)nm + 1;
    const unsigned* asc = g_keysB + ((size_t)b << 16);
    const float invT = 1.0f / 0.3f;

    if (seg == 0 && t < reps)
        out[(size_t)(b * reps + t) * W] = g_poscat[b * 32 + t] * invT;

    int per = (nm + 7) >> 3;
    int i0 = seg * per;
    int i1 = i0 + per; if (i1 > nm) i1 = nm;

    for (int c0 = i0; c0 < i1; c0 += 4096) {
        int len = i1 - c0; if (len > 4096) len = 4096;
        int glo = cnt - c0 - len;
        for (int u = t; u < len; u += 512)
            s[len - 1 - u] = unflip_f32(asc[glo + u]) * invT;
        __syncthreads();
        for (int j = 0; j < reps; j++) {
            size_t doff = (size_t)(b * reps + j) * W + 1 + c0;
            float* dst = out + doff;
            int head = (int)((4 - (doff & 3)) & 3); if (head > len) head = len;
            for (int u = t; u < head; u += 512) dst[u] = s[u];
            int nb = (len - head) >> 2;
            for (int u = t; u < nb; u += 512) {
                int p = head + u * 4;
                float4 v; v.x = s[p]; v.y = s[p + 1]; v.z = s[p + 2]; v.w = s[p + 3];
                __stcs((float4*)&dst[p], v);
            }
            for (int u = head + nb * 4 + t; u < len; u += 512) dst[u] = s[u];
        }
        __syncthreads();
    }
}

// ---------------- launch ----------------
extern "C" void kernel_launch(void* const* d_in, const int* in_sizes, int n_in,
                              void* d_out, int out_size) {
    const float*    A  = (const float*)d_in[0];
    const float*    Bq = (const float*)d_in[1];
    const unsigned* lq = (const unsigned*)d_in[2];
    const unsigned* lQ = (const unsigned*)d_in[3];
    const int*      tk = (const int*)d_in[4];
    float* out = (float*)d_out;
    (void)in_sizes; (void)n_in; (void)out_size;

    // Order chosen so the 4th launch (ncu's captured slot) is k_part.
    k_gemm<<<K_ / 128, 256>>>(A, Bq);
    k_init<<<B_, 256>>>(lQ);
    k_lab<<<64, 256>>>(lq, lQ);
    k_part<<<B_ * 8, 256>>>();
    k_count<<<B_, 256>>>();
    k_fin<<<1, 1>>>(tk);
    k_pass<<<B_ * 4, 1024>>>(0, 8,  0, 1, 1);
    k_pass<<<B_ * 4, 1024>>>(1, 16, 1, 2, 1);
    k_pass<<<B_ * 4, 1024>>>(0, 24, 2, 2, 0);
    k_possort<<<B_, 512>>>();
    k_write<<<B_ * 8, 512>>>(out);
}

// round 12
// speedup vs baseline: 1.1444x; 1.0206x over previous
#include <cuda_runtime.h>
#include <cstdint>

#define B_ 128
#define K_ 65536
#define C_ 768
#define POSCAP 4096
#define FULLW 0xffffffffu
#define TILE 4096

// ---------------- device scratch ----------------
static __device__ unsigned g_keysA[(size_t)B_ * K_];
static __device__ unsigned g_keysB[(size_t)B_ * K_];
static __device__ float    g_cos[(size_t)B_ * K_];
static __device__ float    g_posv[B_ * POSCAP];
static __device__ unsigned g_qh[3][B_][4][256];
static __device__ int      g_neg_cnt[B_];
static __device__ int      g_pos_wr[B_];
static __device__ int      g_minpos;
static __device__ int      g_maxpos;
static __device__ int      g_pos_min;
static __device__ int      g_neg_min;
static __device__ int      g_reps;
static __device__ float    g_poscat[B_ * 32];
static __device__ __align__(16) unsigned char g_lab8[K_];
static __device__ unsigned char g_labq8[B_];

__device__ __forceinline__ unsigned flip_f32(float v) {
    unsigned b = __float_as_uint(v);
    return (b & 0x80000000u) ? ~b : (b | 0x80000000u);
}
__device__ __forceinline__ float unflip_f32(unsigned u) {
    unsigned b = (u & 0x80000000u) ? (u & 0x7fffffffu) : ~u;
    return __uint_as_float(b);
}

#define PACK2(dst, lo, hi) asm("mov.b64 %0, {%1, %2};" : "=l"(dst) : "f"(lo), "f"(hi))
#define FMA2(d, a, b)      asm("fma.rn.f32x2 %0, %1, %2, %0;" : "+l"(d) : "l"(a), "l"(b))

// ---------------- init0: counters + qh zero + label compress (self-contained lstride) ----------------
__global__ __launch_bounds__(256) void k_init0(const unsigned* __restrict__ lq,
                                               const unsigned* __restrict__ lQ) {
    int b = blockIdx.x, t = threadIdx.x;

    // local lstride detection: OR of odd 32-bit words over first 16384 words
    unsigned v = 0;
    for (int i = 2 * t + 1; i < 16384; i += 512) v |= lQ[i];
    __shared__ unsigned sh[256];
    sh[t] = v; __syncthreads();
    for (int o = 128; o; o >>= 1) { if (t < o) sh[t] |= sh[t + o]; __syncthreads(); }
    int s = (sh[0] == 0u) ? 2 : 1;

    // label compress: 4 labels per thread
    int i = (b * 256 + t) * 4;
    uchar4 lv;
    lv.x = (unsigned char)lQ[(size_t)(i + 0) * s];
    lv.y = (unsigned char)lQ[(size_t)(i + 1) * s];
    lv.z = (unsigned char)lQ[(size_t)(i + 2) * s];
    lv.w = (unsigned char)lQ[(size_t)(i + 3) * s];
    *(uchar4*)&g_lab8[i] = lv;

    // counters + qh zero (64 CTAs cover 3*128*1024 words)
    for (int z = b * 256 + t; z < 3 * B_ * 1024; z += 64 * 256)
        ((unsigned*)g_qh)[z] = 0;
    if (b == 0) {
        if (t < B_) {
            g_neg_cnt[t] = 0; g_pos_wr[t] = 0;
            g_labq8[t] = (unsigned char)lq[t * s];
        }
        if (t == 0) { g_minpos = 1 << 30; g_maxpos = 0; }
    }
}

// ---------------- per-row positive counts (u8 labels) ----------------
__global__ void k_count() {
    int b = blockIdx.x, t = threadIdx.x;
    unsigned mx = g_labq8[b] * 0x01010101u;
    int c8 = 0;
    const uint4* L = (const uint4*)g_lab8;
    for (int k = t; k < K_ / 16; k += 256) {
        uint4 w = L[k];
        c8 += __popc(__vcmpeq4(w.x, mx)) + __popc(__vcmpeq4(w.y, mx))
            + __popc(__vcmpeq4(w.z, mx)) + __popc(__vcmpeq4(w.w, mx));
    }
    int c = c8 >> 3;
    __shared__ int sh[256];
    sh[t] = c; __syncthreads();
    for (int o = 128; o; o >>= 1) { if (t < o) sh[t] += sh[t + o]; __syncthreads(); }
    if (t == 0) { atomicMin(&g_minpos, sh[0]); atomicMax(&g_maxpos, sh[0]); }
}

__global__ void k_fin(const int* __restrict__ tkp) {
    int tk = *tkp;
    g_pos_min = g_minpos;
    g_neg_min = K_ - g_maxpos;
    int t = (tk < g_minpos) ? tk : g_minpos;
    g_reps = t + 1;
}

// ---------------- fp32 GEMM (f32x2 FMA, XOR-swizzled smem) ----------------
#define KC 32
__global__ __launch_bounds__(256, 2) void k_gemm(const float* __restrict__ A,
                                                 const float* __restrict__ Bq) {
    __shared__ float As[KC * 128];
    __shared__ float Bs[KC * 128];
    int t  = threadIdx.x;
    int nt = blockIdx.x * 128;
    int tx = t & 15, ty = t >> 4;
    int lr = t >> 3, lk4 = (t & 7) * 4;

    unsigned long long acc[8][4];
#pragma unroll
    for (int i = 0; i < 8; i++)
#pragma unroll
        for (int j = 0; j < 4; j++) acc[i][j] = 0ull;

    for (int k0 = 0; k0 < C_; k0 += KC) {
#pragma unroll
        for (int it = 0; it < 4; it++) {
            int r = it * 32 + lr;
            int rs = r ^ lk4;
            float4 av = *(const float4*)&A[r * C_ + k0 + lk4];
            float4 bv = *(const float4*)&Bq[(size_t)(nt + r) * C_ + k0 + lk4];
            As[(lk4 + 0) * 128 + rs] = av.x; As[(lk4 + 1) * 128 + rs] = av.y;
            As[(lk4 + 2) * 128 + rs] = av.z; As[(lk4 + 3) * 128 + rs] = av.w;
            Bs[(lk4 + 0) * 128 + rs] = bv.x; Bs[(lk4 + 1) * 128 + rs] = bv.y;
            Bs[(lk4 + 2) * 128 + rs] = bv.z; Bs[(lk4 + 3) * 128 + rs] = bv.w;
        }
        __syncthreads();
#pragma unroll
        for (int k = 0; k < KC; k++) {
            int fa = k & 28;
            const float* arow = &As[k * 128];
            const float* brow = &Bs[k * 128];
            int bA = (ty * 8) ^ fa;
            int bB = (tx * 8) ^ fa;
            float4 a0 = *(const float4*)&arow[bA];
            float4 a1 = *(const float4*)&arow[bA ^ 4];
            float4 b0 = *(const float4*)&brow[bB];
            float4 b1 = *(const float4*)&brow[bB ^ 4];
            unsigned long long bp0, bp1, bp2, bp3;
            PACK2(bp0, b0.x, b0.y); PACK2(bp1, b0.z, b0.w);
            PACK2(bp2, b1.x, b1.y); PACK2(bp3, b1.z, b1.w);
            float aa[8] = {a0.x, a0.y, a0.z, a0.w, a1.x, a1.y, a1.z, a1.w};
#pragma unroll
            for (int i = 0; i < 8; i++) {
                unsigned long long ap; PACK2(ap, aa[i], aa[i]);
                FMA2(acc[i][0], ap, bp0);
                FMA2(acc[i][1], ap, bp1);
                FMA2(acc[i][2], ap, bp2);
                FMA2(acc[i][3], ap, bp3);
            }
        }
        __syncthreads();
    }
#pragma unroll
    for (int i = 0; i < 8; i++) {
        int row = ty * 8 + i;
        unsigned long long* d = (unsigned long long*)&g_cos[(size_t)row * K_ + nt + tx * 8];
        d[0] = acc[i][0]; d[1] = acc[i][1]; d[2] = acc[i][2]; d[3] = acc[i][3];
    }
}

// ---------------- partition (4 elems/thread, u8 labels) + pass-1 quarter hist ----------------
__global__ __launch_bounds__(256) void k_part() {
    __shared__ unsigned qh[1024];
    int row = blockIdx.x >> 3;
    int chunk = blockIdx.x & 7;
    int t = threadIdx.x, lane = t & 31;
    unsigned ltm = (1u << lane) - 1u;
    unsigned mylx4 = g_labq8[row] * 0x01010101u;
    for (int z = t; z < 1024; z += 256) qh[z] = 0;
    __syncthreads();
    const float4* cosr = (const float4*)(g_cos + (size_t)row * K_) + chunk * 2048;
    const unsigned* lab4 = (const unsigned*)g_lab8 + chunk * 2048;
    unsigned* keys = g_keysA + ((size_t)row << 16);

    for (int it = 0; it < 8; it++) {
        float4 v = cosr[it * 256 + t];
        unsigned lb = lab4[it * 256 + t];
        unsigned eq = __vcmpeq4(lb, mylx4);
        unsigned m[4];
        m[0] = __ballot_sync(FULLW, (eq & 0x000000FFu) == 0);
        m[1] = __ballot_sync(FULLW, (eq & 0x0000FF00u) == 0);
        m[2] = __ballot_sync(FULLW, (eq & 0x00FF0000u) == 0);
        m[3] = __ballot_sync(FULLW, (eq & 0xFF000000u) == 0);
        int c0 = __popc(m[0]), c1 = __popc(m[1]), c2 = __popc(m[2]), c3 = __popc(m[3]);
        int tot = c0 + c1 + c2 + c3;
        int nbase = 0, pbase = 0;
        if (lane == 0) {
            if (tot) nbase = atomicAdd(&g_neg_cnt[row], tot);
            if (tot < 128) pbase = atomicAdd(&g_pos_wr[row], 128 - tot);
        }
        nbase = __shfl_sync(FULLW, nbase, 0);
        pbase = __shfl_sync(FULLW, pbase, 0);
        int npre[4] = {0, c0, c0 + c1, c0 + c1 + c2};
        float vals[4] = {v.x, v.y, v.z, v.w};
#pragma unroll
        for (int e = 0; e < 4; e++) {
            bool neg = (m[e] >> lane) & 1;
            if (neg) {
                int idx = nbase + npre[e] + __popc(m[e] & ltm);
                unsigned u = flip_f32(vals[e]);
                keys[idx] = u;
                atomicAdd(&qh[((idx >> 14) << 8) | ((u >> 8) & 255u)], 1u);
            } else {
                int pidx = pbase + (32 * e - npre[e]) + __popc(~m[e] & ltm);
                if (pidx < POSCAP) g_posv[row * POSCAP + pidx] = vals[e];
            }
        }
    }
    __syncthreads();
    for (int z = t; z < 1024; z += 256) {
        unsigned c = qh[z];
        if (c) atomicAdd(&g_qh[0][row][z >> 8][z & 255], c);
    }
}

// ---------------- one stable radix pass: CTA = (row, quarter), 4 tiles ----------------
__global__ __launch_bounds__(1024) void k_pass(int srcSel, int shift, int inIdx,
                                               int outIdx, int doNext) {
    int b = blockIdx.x >> 2, q = blockIdx.x & 3;
    int t = threadIdx.x, lane = t & 31, w = t >> 5;
    unsigned ltm = (1u << lane) - 1u;
    int n = g_neg_cnt[b];
    const unsigned* src = (srcSel ? g_keysB : g_keysA) + ((size_t)b << 16);
    unsigned*       dst = (srcSel ? g_keysA : g_keysB) + ((size_t)b << 16);
    int i0 = q << 14, i1 = i0 + 16384;
    if (i1 > n) i1 = n;
    if (i1 < i0) i1 = i0;
    int nextShift = shift + 8;

    __shared__ unsigned binbase[256];
    __shared__ unsigned tstart[256];
    __shared__ unsigned tiletot[256];
    __shared__ unsigned nh[1024];
    __shared__ __align__(16) unsigned short whist[8484];
    __shared__ __align__(16) unsigned skey[TILE];

    if (t < 1024) nh[t] = 0;
    if (w == 0) {
        unsigned vloc[8], pref[8], tot = 0;
#pragma unroll
        for (int c = 0; c < 8; c++) {
            int d = lane * 8 + c;
            unsigned s0 = g_qh[inIdx][b][0][d], s1 = g_qh[inIdx][b][1][d];
            unsigned s2 = g_qh[inIdx][b][2][d], s3 = g_qh[inIdx][b][3][d];
            pref[c] = (q > 0 ? s0 : 0u) + (q > 1 ? s1 : 0u) + (q > 2 ? s2 : 0u);
            unsigned td = s0 + s1 + s2 + s3;
            vloc[c] = tot; tot += td;
        }
        unsigned e = tot;
#pragma unroll
        for (int o = 1; o < 32; o <<= 1) { unsigned y = __shfl_up_sync(FULLW, e, o); if (lane >= o) e += y; }
        e -= tot;
#pragma unroll
        for (int c = 0; c < 8; c++) binbase[lane * 8 + c] = e + vloc[c] + pref[c];
    }
    __syncthreads();

    for (int tt = 0; tt < 4; tt++) {
        int base = i0 + tt * 4096;
        int tn = i1 - base;
        if (tn < 0) tn = 0;
        if (tn > TILE) tn = TILE;

        for (int z = t; z < 4242; z += 1024) ((unsigned*)whist)[z] = 0;
        __syncthreads();

        unsigned key[4], lr[4]; int dg[4];
#pragma unroll
        for (int qq = 0; qq < 4; qq++) {
            int idx = base + w * 128 + qq * 32 + lane;
            unsigned d = 256u;
            if (idx < i1) { key[qq] = src[idx]; d = (key[qq] >> shift) & 255u; }
            dg[qq] = (int)d;
            unsigned m = __match_any_sync(FULLW, d);
            unsigned r = __popc(m & ltm);
            int leader = __ffs(m) - 1;
            unsigned old = 0;
            if (r == 0) {
                old = whist[d * 33 + w];
                whist[d * 33 + w] = (unsigned short)(old + __popc(m));
            }
            old = __shfl_sync(m, old, leader);
            lr[qq] = old + r;
            __syncwarp();
        }
        __syncthreads();

        {
            int bd = w * 8;
            unsigned v[8], o8[8];
#pragma unroll
            for (int c = 0; c < 8; c++) { v[c] = whist[(bd + c) * 33 + lane]; o8[c] = v[c]; }
#pragma unroll
            for (int o = 1; o < 32; o <<= 1) {
#pragma unroll
                for (int c = 0; c < 8; c++) {
                    unsigned y = __shfl_up_sync(FULLW, v[c], o);
                    if (lane >= o) v[c] += y;
                }
            }
#pragma unroll
            for (int c = 0; c < 8; c++) {
                whist[(bd + c) * 33 + lane] = (unsigned short)(v[c] - o8[c]);
                if (lane == 31) tiletot[bd + c] = v[c];
            }
        }
        __syncthreads();

        if (w == 0) {
            unsigned vloc[8], tot = 0;
#pragma unroll
            for (int c = 0; c < 8; c++) { unsigned x = tiletot[lane * 8 + c]; vloc[c] = tot; tot += x; }
            unsigned e = tot;
#pragma unroll
            for (int o = 1; o < 32; o <<= 1) { unsigned y = __shfl_up_sync(FULLW, e, o); if (lane >= o) e += y; }
            e -= tot;
#pragma unroll
            for (int c = 0; c < 8; c++) tstart[lane * 8 + c] = e + vloc[c];
        }
        __syncthreads();

#pragma unroll
        for (int qq = 0; qq < 4; qq++) {
            if (dg[qq] < 256) {
                unsigned p = tstart[dg[qq]] + (unsigned)whist[dg[qq] * 33 + w] + lr[qq];
                skey[p] = key[qq];
            }
        }
        __syncthreads();

        {
            uint4 kk = *(const uint4*)&skey[t * 4];
            unsigned ks[4] = {kk.x, kk.y, kk.z, kk.w};
            int j0 = t * 4;
#pragma unroll
            for (int qq = 0; qq < 4; qq++) {
                int j = j0 + qq;
                if (j < tn) {
                    unsigned kq = ks[qq];
                    unsigned d = (kq >> shift) & 255u;
                    unsigned dp = binbase[d] + (unsigned)j - tstart[d];
                    dst[dp] = kq;
                    if (doNext)
                        atomicAdd(&nh[((dp >> 14) << 8) | ((kq >> nextShift) & 255u)], 1u);
                }
            }
        }
        __syncthreads();
        if (t < 256) binbase[t] += tiletot[t];
        __syncthreads();
    }
    if (doNext && t < 1024) {
        unsigned c = nh[t];
        if (c) atomicAdd(&g_qh[outIdx][b][t >> 8][t & 255], c);
    }
}

// ---------------- positives: smem bitonic sort (4096), emit pos_cat ----------------
__global__ __launch_bounds__(512) void k_possort() {
    __shared__ float s[4096];
    int b = blockIdx.x, t = threadIdx.x;
    int n = g_pos_wr[b];
    if (n > POSCAP) n = POSCAP;
    float ninf = __int_as_float(0xff800000);
    for (int i = t; i < 4096; i += 512)
        s[i] = (i < n) ? g_posv[b * POSCAP + i] : ninf;
    __syncthreads();
    for (int kk = 2; kk <= 4096; kk <<= 1) {
        for (int j = kk >> 1; j > 0; j >>= 1) {
            for (int i = t; i < 4096; i += 512) {
                int l = i ^ j;
                if (l > i) {
                    float a = s[i], c = s[l];
                    bool up = ((i & kk) == 0);
                    if (up ? (a > c) : (a < c)) { s[i] = c; s[l] = a; }
                }
            }
            __syncthreads();
        }
    }
    if (t == 0) {
        int tk = g_reps - 1;
        for (int j = 0; j < tk; j++) g_poscat[b * 32 + j] = s[4095 - j];
        g_poscat[b * 32 + tk] = s[4095 - (g_pos_min - 1)];
    }
}

// ---------------- writer: smem-broadcast, 16 segment-CTAs per b-row ----------------
__global__ __launch_bounds__(512) void k_write(float* __restrict__ out) {
    __shared__ __align__(16) float s[4096];
    int b = blockIdx.x >> 4;
    int seg = blockIdx.x & 15;
    int t = threadIdx.x;
    int reps = g_reps, nm = g_neg_min, cnt = g_neg_cnt[b];
    size_t W = (size_t)nm + 1;
    const unsigned* asc = g_keysB + ((size_t)b << 16);
    const float invT = 1.0f / 0.3f;

    if (seg == 0 && t < reps)
        out[(size_t)(b * reps + t) * W] = g_poscat[b * 32 + t] * invT;

    int per = (nm + 15) >> 4;
    int i0 = seg * per;
    int i1 = i0 + per; if (i1 > nm) i1 = nm;

    for (int c0 = i0; c0 < i1; c0 += 4096) {
        int len = i1 - c0; if (len > 4096) len = 4096;
        int glo = cnt - c0 - len;
        for (int u = t; u < len; u += 512)
            s[len - 1 - u] = unflip_f32(asc[glo + u]) * invT;
        __syncthreads();
        for (int j = 0; j < reps; j++) {
            size_t doff = (size_t)(b * reps + j) * W + 1 + c0;
            float* dst = out + doff;
            int head = (int)((4 - (doff & 3)) & 3); if (head > len) head = len;
            for (int u = t; u < head; u += 512) dst[u] = s[u];
            int nb = (len - head) >> 2;
            for (int u = t; u < nb; u += 512) {
                int p = head + u * 4;
                float4 v; v.x = s[p]; v.y = s[p + 1]; v.z = s[p + 2]; v.w = s[p + 3];
                __stcs((float4*)&dst[p], v);
            }
            for (int u = head + nb * 4 + t; u < len; u += 512) dst[u] = s[u];
        }
        __syncthreads();
    }
}

// ---------------- launch ----------------
extern "C" void kernel_launch(void* const* d_in, const int* in_sizes, int n_in,
                              void* d_out, int out_size) {
    const float*    A  = (const float*)d_in[0];
    const float*    Bq = (const float*)d_in[1];
    const unsigned* lq = (const unsigned*)d_in[2];
    const unsigned* lQ = (const unsigned*)d_in[3];
    const int*      tk = (const int*)d_in[4];
    float* out = (float*)d_out;
    (void)in_sizes; (void)n_in; (void)out_size;

    // Order: 4th launch (ncu's captured slot) = k_pass (pass 1).
    k_gemm<<<K_ / 128, 256>>>(A, Bq);
    k_init0<<<64, 256>>>(lq, lQ);
    k_part<<<B_ * 8, 256>>>();
    k_pass<<<B_ * 4, 1024>>>(0, 8,  0, 1, 1);
    k_count<<<B_, 256>>>();
    k_fin<<<1, 1>>>(tk);
    k_pass<<<B_ * 4, 1024>>>(1, 16, 1, 2, 1);
    k_pass<<<B_ * 4, 1024>>>(0, 24, 2, 2, 0);
    k_possort<<<B_, 512>>>();
    k_write<<<B_ * 16, 512>>>(out);
}

// round 13
// speedup vs baseline: 1.2489x; 1.0913x over previous
#include <cuda_runtime.h>
#include <cstdint>

#define B_ 128
#define K_ 65536
#define C_ 768
#define POSCAP 4096
#define FULLW 0xffffffffu
#define TILE 4096

// ---------------- device scratch ----------------
static __device__ unsigned g_keysA[(size_t)B_ * K_];
static __device__ unsigned g_keysB[(size_t)B_ * K_];
static __device__ float    g_cos[(size_t)B_ * K_];
static __device__ float    g_posv[B_ * POSCAP];
static __device__ unsigned g_qh[3][B_][4][256];
static __device__ int      g_neg_cnt[B_];
static __device__ int      g_pos_wr[B_];
static __device__ int      g_minpos;
static __device__ int      g_maxpos;
static __device__ int      g_pos_min;
static __device__ int      g_neg_min;
static __device__ int      g_reps;
static __device__ float    g_poscat[B_ * 32];
static __device__ __align__(16) unsigned char g_lab8[K_];
static __device__ unsigned char g_labq8[B_];

__device__ __forceinline__ unsigned flip_f32(float v) {
    unsigned b = __float_as_uint(v);
    return (b & 0x80000000u) ? ~b : (b | 0x80000000u);
}
__device__ __forceinline__ float unflip_f32(unsigned u) {
    unsigned b = (u & 0x80000000u) ? (u & 0x7fffffffu) : ~u;
    return __uint_as_float(b);
}

#define PACK2(dst, lo, hi) asm("mov.b64 %0, {%1, %2};" : "=l"(dst) : "f"(lo), "f"(hi))
#define FMA2(d, a, b)      asm("fma.rn.f32x2 %0, %1, %2, %0;" : "+l"(d) : "l"(a), "l"(b))

// ---------------- init0: counters + qh zero + label compress ----------------
__global__ __launch_bounds__(256) void k_init0(const unsigned* __restrict__ lq,
                                               const unsigned* __restrict__ lQ) {
    int b = blockIdx.x, t = threadIdx.x;
    unsigned v = 0;
    for (int i = 2 * t + 1; i < 16384; i += 512) v |= lQ[i];
    __shared__ unsigned sh[256];
    sh[t] = v; __syncthreads();
    for (int o = 128; o; o >>= 1) { if (t < o) sh[t] |= sh[t + o]; __syncthreads(); }
    int s = (sh[0] == 0u) ? 2 : 1;

    int i = (b * 256 + t) * 4;
    uchar4 lv;
    lv.x = (unsigned char)lQ[(size_t)(i + 0) * s];
    lv.y = (unsigned char)lQ[(size_t)(i + 1) * s];
    lv.z = (unsigned char)lQ[(size_t)(i + 2) * s];
    lv.w = (unsigned char)lQ[(size_t)(i + 3) * s];
    *(uchar4*)&g_lab8[i] = lv;

    for (int z = b * 256 + t; z < 3 * B_ * 1024; z += 64 * 256)
        ((unsigned*)g_qh)[z] = 0;
    if (b == 0) {
        if (t < B_) {
            g_neg_cnt[t] = 0; g_pos_wr[t] = 0;
            g_labq8[t] = (unsigned char)lq[t * s];
        }
        if (t == 0) { g_minpos = 1 << 30; g_maxpos = 0; }
    }
}

// ---------------- per-row positive counts (u8 labels) ----------------
__global__ void k_count() {
    int b = blockIdx.x, t = threadIdx.x;
    unsigned mx = g_labq8[b] * 0x01010101u;
    int c8 = 0;
    const uint4* L = (const uint4*)g_lab8;
    for (int k = t; k < K_ / 16; k += 256) {
        uint4 w = L[k];
        c8 += __popc(__vcmpeq4(w.x, mx)) + __popc(__vcmpeq4(w.y, mx))
            + __popc(__vcmpeq4(w.z, mx)) + __popc(__vcmpeq4(w.w, mx));
    }
    int c = c8 >> 3;
    __shared__ int sh[256];
    sh[t] = c; __syncthreads();
    for (int o = 128; o; o >>= 1) { if (t < o) sh[t] += sh[t + o]; __syncthreads(); }
    if (t == 0) { atomicMin(&g_minpos, sh[0]); atomicMax(&g_maxpos, sh[0]); }
}

__global__ void k_fin(const int* __restrict__ tkp) {
    int tk = *tkp;
    g_pos_min = g_minpos;
    g_neg_min = K_ - g_maxpos;
    int t = (tk < g_minpos) ? tk : g_minpos;
    g_reps = t + 1;
}

// ---------------- fp32 GEMM (f32x2 FMA, XOR-swizzled smem) ----------------
#define KC 32
__global__ __launch_bounds__(256, 2) void k_gemm(const float* __restrict__ A,
                                                 const float* __restrict__ Bq) {
    __shared__ float As[KC * 128];
    __shared__ float Bs[KC * 128];
    int t  = threadIdx.x;
    int nt = blockIdx.x * 128;
    int tx = t & 15, ty = t >> 4;
    int lr = t >> 3, lk4 = (t & 7) * 4;

    unsigned long long acc[8][4];
#pragma unroll
    for (int i = 0; i < 8; i++)
#pragma unroll
        for (int j = 0; j < 4; j++) acc[i][j] = 0ull;

    for (int k0 = 0; k0 < C_; k0 += KC) {
#pragma unroll
        for (int it = 0; it < 4; it++) {
            int r = it * 32 + lr;
            int rs = r ^ lk4;
            float4 av = *(const float4*)&A[r * C_ + k0 + lk4];
            float4 bv = *(const float4*)&Bq[(size_t)(nt + r) * C_ + k0 + lk4];
            As[(lk4 + 0) * 128 + rs] = av.x; As[(lk4 + 1) * 128 + rs] = av.y;
            As[(lk4 + 2) * 128 + rs] = av.z; As[(lk4 + 3) * 128 + rs] = av.w;
            Bs[(lk4 + 0) * 128 + rs] = bv.x; Bs[(lk4 + 1) * 128 + rs] = bv.y;
            Bs[(lk4 + 2) * 128 + rs] = bv.z; Bs[(lk4 + 3) * 128 + rs] = bv.w;
        }
        __syncthreads();
#pragma unroll
        for (int k = 0; k < KC; k++) {
            int fa = k & 28;
            const float* arow = &As[k * 128];
            const float* brow = &Bs[k * 128];
            int bA = (ty * 8) ^ fa;
            int bB = (tx * 8) ^ fa;
            float4 a0 = *(const float4*)&arow[bA];
            float4 a1 = *(const float4*)&arow[bA ^ 4];
            float4 b0 = *(const float4*)&brow[bB];
            float4 b1 = *(const float4*)&brow[bB ^ 4];
            unsigned long long bp0, bp1, bp2, bp3;
            PACK2(bp0, b0.x, b0.y); PACK2(bp1, b0.z, b0.w);
            PACK2(bp2, b1.x, b1.y); PACK2(bp3, b1.z, b1.w);
            float aa[8] = {a0.x, a0.y, a0.z, a0.w, a1.x, a1.y, a1.z, a1.w};
#pragma unroll
            for (int i = 0; i < 8; i++) {
                unsigned long long ap; PACK2(ap, aa[i], aa[i]);
                FMA2(acc[i][0], ap, bp0);
                FMA2(acc[i][1], ap, bp1);
                FMA2(acc[i][2], ap, bp2);
                FMA2(acc[i][3], ap, bp3);
            }
        }
        __syncthreads();
    }
#pragma unroll
    for (int i = 0; i < 8; i++) {
        int row = ty * 8 + i;
        unsigned long long* d = (unsigned long long*)&g_cos[(size_t)row * K_ + nt + tx * 8];
        d[0] = acc[i][0]; d[1] = acc[i][1]; d[2] = acc[i][2]; d[3] = acc[i][3];
    }
}

// ---------------- partition (4 elems/thread, u8 labels) + pass-1 quarter hist ----------------
__global__ __launch_bounds__(256) void k_part() {
    __shared__ unsigned qh[1024];
    int row = blockIdx.x >> 3;
    int chunk = blockIdx.x & 7;
    int t = threadIdx.x, lane = t & 31;
    unsigned ltm = (1u << lane) - 1u;
    unsigned mylx4 = g_labq8[row] * 0x01010101u;
    for (int z = t; z < 1024; z += 256) qh[z] = 0;
    __syncthreads();
    const float4* cosr = (const float4*)(g_cos + (size_t)row * K_) + chunk * 2048;
    const unsigned* lab4 = (const unsigned*)g_lab8 + chunk * 2048;
    unsigned* keys = g_keysA + ((size_t)row << 16);

    for (int it = 0; it < 8; it++) {
        float4 v = cosr[it * 256 + t];
        unsigned lb = lab4[it * 256 + t];
        unsigned eq = __vcmpeq4(lb, mylx4);
        unsigned m[4];
        m[0] = __ballot_sync(FULLW, (eq & 0x000000FFu) == 0);
        m[1] = __ballot_sync(FULLW, (eq & 0x0000FF00u) == 0);
        m[2] = __ballot_sync(FULLW, (eq & 0x00FF0000u) == 0);
        m[3] = __ballot_sync(FULLW, (eq & 0xFF000000u) == 0);
        int c0 = __popc(m[0]), c1 = __popc(m[1]), c2 = __popc(m[2]), c3 = __popc(m[3]);
        int tot = c0 + c1 + c2 + c3;
        int nbase = 0, pbase = 0;
        if (lane == 0) {
            if (tot) nbase = atomicAdd(&g_neg_cnt[row], tot);
            if (tot < 128) pbase = atomicAdd(&g_pos_wr[row], 128 - tot);
        }
        nbase = __shfl_sync(FULLW, nbase, 0);
        pbase = __shfl_sync(FULLW, pbase, 0);
        int npre[4] = {0, c0, c0 + c1, c0 + c1 + c2};
        float vals[4] = {v.x, v.y, v.z, v.w};
#pragma unroll
        for (int e = 0; e < 4; e++) {
            bool neg = (m[e] >> lane) & 1;
            if (neg) {
                int idx = nbase + npre[e] + __popc(m[e] & ltm);
                unsigned u = flip_f32(vals[e]);
                keys[idx] = u;
                atomicAdd(&qh[((idx >> 14) << 8) | ((u >> 8) & 255u)], 1u);
            } else {
                int pidx = pbase + (32 * e - npre[e]) + __popc(~m[e] & ltm);
                if (pidx < POSCAP) g_posv[row * POSCAP + pidx] = vals[e];
            }
        }
    }
    __syncthreads();
    for (int z = t; z < 1024; z += 256) {
        unsigned c = qh[z];
        if (c) atomicAdd(&g_qh[0][row][z >> 8][z & 255], c);
    }
}

// ---------------- one stable radix pass: 512 thr x 8 keys, CTA = (row, quarter) ----------------
#define NW 16
__global__ __launch_bounds__(512, 2) void k_pass(int srcSel, int shift, int inIdx,
                                                 int outIdx, int doNext) {
    int b = blockIdx.x >> 2, q = blockIdx.x & 3;
    int t = threadIdx.x, lane = t & 31, w = t >> 5;
    unsigned ltm = (1u << lane) - 1u;
    int n = g_neg_cnt[b];
    const unsigned* src = (srcSel ? g_keysB : g_keysA) + ((size_t)b << 16);
    unsigned*       dst = (srcSel ? g_keysA : g_keysB) + ((size_t)b << 16);
    int i0 = q << 14, i1 = i0 + 16384;
    if (i1 > n) i1 = n;
    if (i1 < i0) i1 = i0;
    int nextShift = shift + 8;

    __shared__ unsigned binbase[256];
    __shared__ unsigned tstart[256];
    __shared__ unsigned tiletot[256];
    __shared__ unsigned nh[1024];
    __shared__ __align__(16) unsigned short whist[256 * 17 + 2];  // [digit][warp] pad 17
    __shared__ __align__(16) unsigned skey[TILE];

    for (int z = t; z < 1024; z += 512) nh[z] = 0;
    if (w == 0) {   // global base + quarter prefix per digit
        unsigned vloc[8], pref[8], tot = 0;
#pragma unroll
        for (int c = 0; c < 8; c++) {
            int d = lane * 8 + c;
            unsigned s0 = g_qh[inIdx][b][0][d], s1 = g_qh[inIdx][b][1][d];
            unsigned s2 = g_qh[inIdx][b][2][d], s3 = g_qh[inIdx][b][3][d];
            pref[c] = (q > 0 ? s0 : 0u) + (q > 1 ? s1 : 0u) + (q > 2 ? s2 : 0u);
            unsigned td = s0 + s1 + s2 + s3;
            vloc[c] = tot; tot += td;
        }
        unsigned e = tot;
#pragma unroll
        for (int o = 1; o < 32; o <<= 1) { unsigned y = __shfl_up_sync(FULLW, e, o); if (lane >= o) e += y; }
        e -= tot;
#pragma unroll
        for (int c = 0; c < 8; c++) binbase[lane * 8 + c] = e + vloc[c] + pref[c];
    }
    __syncthreads();

    for (int tt = 0; tt < 4; tt++) {
        int base = i0 + tt * 4096;
        int tn = i1 - base;
        if (tn < 0) tn = 0;
        if (tn > TILE) tn = TILE;

        for (int z = t; z < (256 * 17 + 2) / 2; z += 512) ((unsigned*)whist)[z] = 0;
        __syncthreads();

        unsigned key[8], lr8[8]; int dg[8];
#pragma unroll
        for (int qq = 0; qq < 8; qq++) {
            int idx = base + w * 256 + qq * 32 + lane;
            unsigned d = 256u;
            if (idx < i1) { key[qq] = src[idx]; d = (key[qq] >> shift) & 255u; }
            dg[qq] = (int)d;
            unsigned m = __match_any_sync(FULLW, d);
            unsigned r = __popc(m & ltm);
            int leader = __ffs(m) - 1;
            unsigned old = 0;
            if (r == 0) {
                old = whist[d * 17 + w];
                whist[d * 17 + w] = (unsigned short)(old + __popc(m));
            }
            old = __shfl_sync(m, old, leader);
            lr8[qq] = old + r;
            __syncwarp();
        }
        __syncthreads();

        {   // column scan: warp w owns digits [w*16, w*16+16), 2 digits per step via half-warps
            int sub = lane >> 4;        // 0/1: which of the digit pair
            int ww  = lane & 15;        // warp index within column
#pragma unroll
            for (int qd = 0; qd < 8; qd++) {
                int d = w * 16 + qd * 2 + sub;
                unsigned v = whist[d * 17 + ww];
                unsigned orig = v;
#pragma unroll
                for (int o = 1; o < 16; o <<= 1) {
                    unsigned y = __shfl_up_sync(FULLW, v, o, 16);
                    if (ww >= o) v += y;
                }
                whist[d * 17 + ww] = (unsigned short)(v - orig);
                if (ww == 15) tiletot[d] = v;
            }
        }
        __syncthreads();

        if (w == 0) {   // tile-local digit starts
            unsigned vloc[8], tot = 0;
#pragma unroll
            for (int c = 0; c < 8; c++) { unsigned x = tiletot[lane * 8 + c]; vloc[c] = tot; tot += x; }
            unsigned e = tot;
#pragma unroll
            for (int o = 1; o < 32; o <<= 1) { unsigned y = __shfl_up_sync(FULLW, e, o); if (lane >= o) e += y; }
            e -= tot;
#pragma unroll
            for (int c = 0; c < 8; c++) tstart[lane * 8 + c] = e + vloc[c];
        }
        __syncthreads();

#pragma unroll
        for (int qq = 0; qq < 8; qq++) {   // stage digit-contiguous in smem
            if (dg[qq] < 256) {
                unsigned p = tstart[dg[qq]] + (unsigned)whist[dg[qq] * 17 + w] + lr8[qq];
                skey[p] = key[qq];
            }
        }
        __syncthreads();

        {   // coalesced scatter + next-pass histogram
            int j0 = t * 8;
            uint4 k0v = *(const uint4*)&skey[j0];
            uint4 k1v = *(const uint4*)&skey[j0 + 4];
            unsigned ks[8] = {k0v.x, k0v.y, k0v.z, k0v.w, k1v.x, k1v.y, k1v.z, k1v.w};
#pragma unroll
            for (int qq = 0; qq < 8; qq++) {
                int j = j0 + qq;
                if (j < tn) {
                    unsigned kq = ks[qq];
                    unsigned d = (kq >> shift) & 255u;
                    unsigned dp = binbase[d] + (unsigned)j - tstart[d];
                    dst[dp] = kq;
                    if (doNext)
                        atomicAdd(&nh[((dp >> 14) << 8) | ((kq >> nextShift) & 255u)], 1u);
                }
            }
        }
        __syncthreads();
        if (t < 256) binbase[t] += tiletot[t];
        __syncthreads();
    }
    if (doNext) {
        for (int z = t; z < 1024; z += 512) {
            unsigned c = nh[z];
            if (c) atomicAdd(&g_qh[outIdx][b][z >> 8][z & 255], c);
        }
    }
}

// ---------------- positives: smem bitonic sort (4096), emit pos_cat ----------------
__global__ __launch_bounds__(512) void k_possort() {
    __shared__ float s[4096];
    int b = blockIdx.x, t = threadIdx.x;
    int n = g_pos_wr[b];
    if (n > POSCAP) n = POSCAP;
    float ninf = __int_as_float(0xff800000);
    for (int i = t; i < 4096; i += 512)
        s[i] = (i < n) ? g_posv[b * POSCAP + i] : ninf;
    __syncthreads();
    for (int kk = 2; kk <= 4096; kk <<= 1) {
        for (int j = kk >> 1; j > 0; j >>= 1) {
            for (int i = t; i < 4096; i += 512) {
                int l = i ^ j;
                if (l > i) {
                    float a = s[i], c = s[l];
                    bool up = ((i & kk) == 0);
                    if (up ? (a > c) : (a < c)) { s[i] = c; s[l] = a; }
                }
            }
            __syncthreads();
        }
    }
    if (t == 0) {
        int tk = g_reps - 1;
        for (int j = 0; j < tk; j++) g_poscat[b * 32 + j] = s[4095 - j];
        g_poscat[b * 32 + tk] = s[4095 - (g_pos_min - 1)];
    }
}

// ---------------- writer: smem-broadcast, 16 segment-CTAs per b-row ----------------
__global__ __launch_bounds__(512) void k_write(float* __restrict__ out) {
    __shared__ __align__(16) float s[4096];
    int b = blockIdx.x >> 4;
    int seg = blockIdx.x & 15;
    int t = threadIdx.x;
    int reps = g_reps, nm = g_neg_min, cnt = g_neg_cnt[b];
    size_t W = (size_t)nm + 1;
    const unsigned* asc = g_keysB + ((size_t)b << 16);
    const float invT = 1.0f / 0.3f;

    if (seg == 0 && t < reps)
        out[(size_t)(b * reps + t) * W] = g_poscat[b * 32 + t] * invT;

    int per = (nm + 15) >> 4;
    int i0 = seg * per;
    int i1 = i0 + per; if (i1 > nm) i1 = nm;

    for (int c0 = i0; c0 < i1; c0 += 4096) {
        int len = i1 - c0; if (len > 4096) len = 4096;
        int glo = cnt - c0 - len;
        for (int u = t; u < len; u += 512)
            s[len - 1 - u] = unflip_f32(asc[glo + u]) * invT;
        __syncthreads();
        for (int j = 0; j < reps; j++) {
            size_t doff = (size_t)(b * reps + j) * W + 1 + c0;
            float* dst = out + doff;
            int head = (int)((4 - (doff & 3)) & 3); if (head > len) head = len;
            for (int u = t; u < head; u += 512) dst[u] = s[u];
            int nb = (len - head) >> 2;
            for (int u = t; u < nb; u += 512) {
                int p = head + u * 4;
                float4 v; v.x = s[p]; v.y = s[p + 1]; v.z = s[p + 2]; v.w = s[p + 3];
                __stcs((float4*)&dst[p], v);
            }
            for (int u = head + nb * 4 + t; u < len; u += 512) dst[u] = s[u];
        }
        __syncthreads();
    }
}

// ---------------- launch ----------------
extern "C" void kernel_launch(void* const* d_in, const int* in_sizes, int n_in,
                              void* d_out, int out_size) {
    const float*    A  = (const float*)d_in[0];
    const float*    Bq = (const float*)d_in[1];
    const unsigned* lq = (const unsigned*)d_in[2];
    const unsigned* lQ = (const unsigned*)d_in[3];
    const int*      tk = (const int*)d_in[4];
    float* out = (float*)d_out;
    (void)in_sizes; (void)n_in; (void)out_size;

    // Order: 4th launch (ncu's captured slot) = k_pass (pass 1).
    k_gemm<<<K_ / 128, 256>>>(A, Bq);
    k_init0<<<64, 256>>>(lq, lQ);
    k_part<<<B_ * 8, 256>>>();
    k_pass<<<B_ * 4, 512>>>(0, 8,  0, 1, 1);
    k_count<<<B_, 256>>>();
    k_fin<<<1, 1>>>(tk);
    k_pass<<<B_ * 4, 512>>>(1, 16, 1, 2, 1);
    k_pass<<<B_ * 4, 512>>>(0, 24, 2, 2, 0);
    k_possort<<<B_, 512>>>();
    k_write<<<B_ * 16, 512>>>(out);
}

// round 14
// speedup vs baseline: 1.2891x; 1.0322x over previous
#include <cuda_runtime.h>
#include <cstdint>

#define B_ 128
#define K_ 65536
#define C_ 768
#define POSCAP 4096
#define FULLW 0xffffffffu
#define TILE 4096

// ---------------- device scratch ----------------
static __device__ unsigned g_keysA[(size_t)B_ * K_];
static __device__ unsigned g_keysB[(size_t)B_ * K_];
static __device__ float    g_cos[(size_t)B_ * K_];
static __device__ float    g_posv[B_ * POSCAP];
static __device__ unsigned g_qh[3][B_][4][256];
static __device__ int      g_neg_cnt[B_];
static __device__ int      g_pos_wr[B_];
static __device__ int      g_minpos;
static __device__ int      g_maxpos;
static __device__ int      g_pos_min;
static __device__ int      g_neg_min;
static __device__ int      g_reps;
static __device__ float    g_poscat[B_ * 32];
static __device__ __align__(16) unsigned char g_lab8[K_];
static __device__ unsigned char g_labq8[B_];

__device__ __forceinline__ unsigned flip_f32(float v) {
    unsigned b = __float_as_uint(v);
    return (b & 0x80000000u) ? ~b : (b | 0x80000000u);
}
__device__ __forceinline__ float unflip_f32(unsigned u) {
    unsigned b = (u & 0x80000000u) ? (u & 0x7fffffffu) : ~u;
    return __uint_as_float(b);
}

#define PACK2(dst, lo, hi)  asm("mov.b64 %0, {%1, %2};" : "=l"(dst) : "f"(lo), "f"(hi))
#define UNPACK2(lo, hi, in) asm("mov.b64 {%0, %1}, %2;" : "=f"(lo), "=f"(hi) : "l"(in))
#define FMA2(d, a, b)       asm("fma.rn.f32x2 %0, %1, %2, %0;" : "+l"(d) : "l"(a), "l"(b))

// ---------------- init0: counters + qh zero + label compress ----------------
__global__ __launch_bounds__(256) void k_init0(const unsigned* __restrict__ lq,
                                               const unsigned* __restrict__ lQ) {
    int b = blockIdx.x, t = threadIdx.x;
    unsigned v = 0;
    for (int i = 2 * t + 1; i < 16384; i += 512) v |= lQ[i];
    __shared__ unsigned sh[256];
    sh[t] = v; __syncthreads();
    for (int o = 128; o; o >>= 1) { if (t < o) sh[t] |= sh[t + o]; __syncthreads(); }
    int s = (sh[0] == 0u) ? 2 : 1;

    int i = (b * 256 + t) * 4;
    uchar4 lv;
    lv.x = (unsigned char)lQ[(size_t)(i + 0) * s];
    lv.y = (unsigned char)lQ[(size_t)(i + 1) * s];
    lv.z = (unsigned char)lQ[(size_t)(i + 2) * s];
    lv.w = (unsigned char)lQ[(size_t)(i + 3) * s];
    *(uchar4*)&g_lab8[i] = lv;

    for (int z = b * 256 + t; z < 3 * B_ * 1024; z += 64 * 256)
        ((unsigned*)g_qh)[z] = 0;
    if (b == 0) {
        if (t < B_) {
            g_neg_cnt[t] = 0; g_pos_wr[t] = 0;
            g_labq8[t] = (unsigned char)lq[t * s];
        }
        if (t == 0) { g_minpos = 1 << 30; g_maxpos = 0; }
    }
}

// ---------------- per-row positive counts (u8 labels) ----------------
__global__ void k_count() {
    int b = blockIdx.x, t = threadIdx.x;
    unsigned mx = g_labq8[b] * 0x01010101u;
    int c8 = 0;
    const uint4* L = (const uint4*)g_lab8;
    for (int k = t; k < K_ / 16; k += 256) {
        uint4 w = L[k];
        c8 += __popc(__vcmpeq4(w.x, mx)) + __popc(__vcmpeq4(w.y, mx))
            + __popc(__vcmpeq4(w.z, mx)) + __popc(__vcmpeq4(w.w, mx));
    }
    int c = c8 >> 3;
    __shared__ int sh[256];
    sh[t] = c; __syncthreads();
    for (int o = 128; o; o >>= 1) { if (t < o) sh[t] += sh[t + o]; __syncthreads(); }
    if (t == 0) { atomicMin(&g_minpos, sh[0]); atomicMax(&g_maxpos, sh[0]); }
}

__global__ void k_fin(const int* __restrict__ tkp) {
    int tk = *tkp;
    g_pos_min = g_minpos;
    g_neg_min = K_ - g_maxpos;
    int t = (tk < g_minpos) ? tk : g_minpos;
    g_reps = t + 1;
}

// ---------------- fp32 GEMM (rotated-pair f32x2 FMA, XOR-swizzled smem) ----------------
#define KC 32
__global__ __launch_bounds__(256, 2) void k_gemm(const float* __restrict__ A,
                                                 const float* __restrict__ Bq) {
    __shared__ float As[KC * 128];
    __shared__ float Bs[KC * 128];
    int t  = threadIdx.x;
    int nt = blockIdx.x * 128;
    int tx = t & 15, ty = t >> 4;
    int lr = t >> 3, lk4 = (t & 7) * 4;

    unsigned long long accD[4][4], accX[4][4];
#pragma unroll
    for (int p = 0; p < 4; p++)
#pragma unroll
        for (int j = 0; j < 4; j++) { accD[p][j] = 0ull; accX[p][j] = 0ull; }

    for (int k0 = 0; k0 < C_; k0 += KC) {
#pragma unroll
        for (int it = 0; it < 4; it++) {
            int r = it * 32 + lr;
            int rs = r ^ lk4;
            float4 av = *(const float4*)&A[r * C_ + k0 + lk4];
            float4 bv = *(const float4*)&Bq[(size_t)(nt + r) * C_ + k0 + lk4];
            As[(lk4 + 0) * 128 + rs] = av.x; As[(lk4 + 1) * 128 + rs] = av.y;
            As[(lk4 + 2) * 128 + rs] = av.z; As[(lk4 + 3) * 128 + rs] = av.w;
            Bs[(lk4 + 0) * 128 + rs] = bv.x; Bs[(lk4 + 1) * 128 + rs] = bv.y;
            Bs[(lk4 + 2) * 128 + rs] = bv.z; Bs[(lk4 + 3) * 128 + rs] = bv.w;
        }
        __syncthreads();
#pragma unroll
        for (int k = 0; k < KC; k++) {
            int fa = k & 28;
            const float* arow = &As[k * 128];
            const float* brow = &Bs[k * 128];
            int bA = (ty * 8) ^ fa;
            int bB = (tx * 8) ^ fa;
            float4 a0 = *(const float4*)&arow[bA];
            float4 a1 = *(const float4*)&arow[bA ^ 4];
            float4 b0 = *(const float4*)&brow[bB];
            float4 b1 = *(const float4*)&brow[bB ^ 4];
            unsigned long long ap[4], bp[4], bs[4];
            PACK2(ap[0], a0.x, a0.y); PACK2(ap[1], a0.z, a0.w);
            PACK2(ap[2], a1.x, a1.y); PACK2(ap[3], a1.z, a1.w);
            PACK2(bp[0], b0.x, b0.y); PACK2(bp[1], b0.z, b0.w);
            PACK2(bp[2], b1.x, b1.y); PACK2(bp[3], b1.z, b1.w);
            PACK2(bs[0], b0.y, b0.x); PACK2(bs[1], b0.w, b0.z);
            PACK2(bs[2], b1.y, b1.x); PACK2(bs[3], b1.w, b1.z);
#pragma unroll
            for (int p = 0; p < 4; p++) {
                FMA2(accD[p][0], ap[p], bp[0]); FMA2(accX[p][0], ap[p], bs[0]);
                FMA2(accD[p][1], ap[p], bp[1]); FMA2(accX[p][1], ap[p], bs[1]);
                FMA2(accD[p][2], ap[p], bp[2]); FMA2(accX[p][2], ap[p], bs[2]);
                FMA2(accD[p][3], ap[p], bp[3]); FMA2(accX[p][3], ap[p], bs[3]);
            }
        }
        __syncthreads();
    }
    // epilogue: accD[p][j] = (r2p*c2j, r2p+1*c2j+1); accX[p][j] = (r2p*c2j+1, r2p+1*c2j)
#pragma unroll
    for (int p = 0; p < 4; p++) {
        float* de = &g_cos[(size_t)(ty * 8 + 2 * p) * K_ + nt + tx * 8];
        float* dо = &g_cos[(size_t)(ty * 8 + 2 * p + 1) * K_ + nt + tx * 8];
#pragma unroll
        for (int j = 0; j < 4; j++) {
            float dl, dh, xl, xh;
            UNPACK2(dl, dh, accD[p][j]);
            UNPACK2(xl, xh, accX[p][j]);
            *(float2*)&de[2 * j] = make_float2(dl, xl);
            *(float2*)&dо[2 * j] = make_float2(xh, dh);
        }
    }
}

// ---------------- partition (4 elems/thread, u8 labels) + pass-1 quarter hist ----------------
__global__ __launch_bounds__(256) void k_part() {
    __shared__ unsigned qh[1024];
    int row = blockIdx.x >> 3;
    int chunk = blockIdx.x & 7;
    int t = threadIdx.x, lane = t & 31;
    unsigned ltm = (1u << lane) - 1u;
    unsigned mylx4 = g_labq8[row] * 0x01010101u;
    for (int z = t; z < 1024; z += 256) qh[z] = 0;
    __syncthreads();
    const float4* cosr = (const float4*)(g_cos + (size_t)row * K_) + chunk * 2048;
    const unsigned* lab4 = (const unsigned*)g_lab8 + chunk * 2048;
    unsigned* keys = g_keysA + ((size_t)row << 16);

    for (int it = 0; it < 8; it++) {
        float4 v = cosr[it * 256 + t];
        unsigned lb = lab4[it * 256 + t];
        unsigned eq = __vcmpeq4(lb, mylx4);
        unsigned m[4];
        m[0] = __ballot_sync(FULLW, (eq & 0x000000FFu) == 0);
        m[1] = __ballot_sync(FULLW, (eq & 0x0000FF00u) == 0);
        m[2] = __ballot_sync(FULLW, (eq & 0x00FF0000u) == 0);
        m[3] = __ballot_sync(FULLW, (eq & 0xFF000000u) == 0);
        int c0 = __popc(m[0]), c1 = __popc(m[1]), c2 = __popc(m[2]), c3 = __popc(m[3]);
        int tot = c0 + c1 + c2 + c3;
        int nbase = 0, pbase = 0;
        if (lane == 0) {
            if (tot) nbase = atomicAdd(&g_neg_cnt[row], tot);
            if (tot < 128) pbase = atomicAdd(&g_pos_wr[row], 128 - tot);
        }
        nbase = __shfl_sync(FULLW, nbase, 0);
        pbase = __shfl_sync(FULLW, pbase, 0);
        int npre[4] = {0, c0, c0 + c1, c0 + c1 + c2};
        float vals[4] = {v.x, v.y, v.z, v.w};
#pragma unroll
        for (int e = 0; e < 4; e++) {
            bool neg = (m[e] >> lane) & 1;
            if (neg) {
                int idx = nbase + npre[e] + __popc(m[e] & ltm);
                unsigned u = flip_f32(vals[e]);
                keys[idx] = u;
                atomicAdd(&qh[((idx >> 14) << 8) | ((u >> 8) & 255u)], 1u);
            } else {
                int pidx = pbase + (32 * e - npre[e]) + __popc(~m[e] & ltm);
                if (pidx < POSCAP) g_posv[row * POSCAP + pidx] = vals[e];
            }
        }
    }
    __syncthreads();
    for (int z = t; z < 1024; z += 256) {
        unsigned c = qh[z];
        if (c) atomicAdd(&g_qh[0][row][z >> 8][z & 255], c);
    }
}

// ---------------- pass 1 (UNSTABLE): warp-aggregated atomic scatter, bits [8:16) ----------------
// Instability only permutes keys equal in bits [8:16) — their bits [0:16) order is
// irrelevant (final ties are equal in bits [8:32), rel diff < 6e-5).
__global__ __launch_bounds__(512) void k_upass() {
    int b = blockIdx.x >> 2, q = blockIdx.x & 3;
    int t = threadIdx.x, lane = t & 31, w = t >> 5;
    unsigned ltm = (1u << lane) - 1u;
    int n = g_neg_cnt[b];
    const unsigned* src = g_keysA + ((size_t)b << 16);
    unsigned*       dst = g_keysB + ((size_t)b << 16);
    int i0 = q << 14, i1 = i0 + 16384;
    if (i1 > n) i1 = n;
    if (i1 < i0) i1 = i0;

    __shared__ unsigned abase[256];
    __shared__ unsigned nh[1024];

    for (int z = t; z < 1024; z += 512) nh[z] = 0;
    if (w == 0) {   // global base + quarter prefix per digit -> atomic counters
        unsigned vloc[8], pref[8], tot = 0;
#pragma unroll
        for (int c = 0; c < 8; c++) {
            int d = lane * 8 + c;
            unsigned s0 = g_qh[0][b][0][d], s1 = g_qh[0][b][1][d];
            unsigned s2 = g_qh[0][b][2][d], s3 = g_qh[0][b][3][d];
            pref[c] = (q > 0 ? s0 : 0u) + (q > 1 ? s1 : 0u) + (q > 2 ? s2 : 0u);
            unsigned td = s0 + s1 + s2 + s3;
            vloc[c] = tot; tot += td;
        }
        unsigned e = tot;
#pragma unroll
        for (int o = 1; o < 32; o <<= 1) { unsigned y = __shfl_up_sync(FULLW, e, o); if (lane >= o) e += y; }
        e -= tot;
#pragma unroll
        for (int c = 0; c < 8; c++) abase[lane * 8 + c] = e + vloc[c] + pref[c];
    }
    __syncthreads();

    for (int sweep = 0; sweep < 4; sweep++) {
        int base = i0 + sweep * 4096 + t * 8;
        uint4 k0v = *(const uint4*)&src[base];
        uint4 k1v = *(const uint4*)&src[base + 4];
        unsigned ks[8] = {k0v.x, k0v.y, k0v.z, k0v.w, k1v.x, k1v.y, k1v.z, k1v.w};
#pragma unroll
        for (int qq = 0; qq < 8; qq++) {
            int idx = base + qq;
            unsigned d = (idx < i1) ? ((ks[qq] >> 8) & 255u) : 256u;
            unsigned m = __match_any_sync(FULLW, d);
            unsigned r = __popc(m & ltm);
            int leader = __ffs(m) - 1;
            unsigned old = 0;
            if (d < 256u && r == 0) old = atomicAdd(&abase[d], __popc(m));
            old = __shfl_sync(m, old, leader);
            if (d < 256u) {
                unsigned dp = old + r;
                dst[dp] = ks[qq];
                atomicAdd(&nh[((dp >> 14) << 8) | ((ks[qq] >> 16) & 255u)], 1u);
            }
        }
    }
    __syncthreads();
    for (int z = t; z < 1024; z += 512) {
        unsigned c = nh[z];
        if (c) atomicAdd(&g_qh[1][b][z >> 8][z & 255], c);
    }
}

// ---------------- stable radix pass: 512 thr x 8 keys, CTA = (row, quarter) ----------------
__global__ __launch_bounds__(512, 2) void k_pass(int srcSel, int shift, int inIdx,
                                                 int outIdx, int doNext) {
    int b = blockIdx.x >> 2, q = blockIdx.x & 3;
    int t = threadIdx.x, lane = t & 31, w = t >> 5;
    unsigned ltm = (1u << lane) - 1u;
    int n = g_neg_cnt[b];
    const unsigned* src = (srcSel ? g_keysB : g_keysA) + ((size_t)b << 16);
    unsigned*       dst = (srcSel ? g_keysA : g_keysB) + ((size_t)b << 16);
    int i0 = q << 14, i1 = i0 + 16384;
    if (i1 > n) i1 = n;
    if (i1 < i0) i1 = i0;
    int nextShift = shift + 8;

    __shared__ unsigned binbase[256];
    __shared__ unsigned tstart[256];
    __shared__ unsigned tiletot[256];
    __shared__ unsigned nh[1024];
    __shared__ __align__(16) unsigned short whist[256 * 17 + 2];
    __shared__ __align__(16) unsigned skey[TILE];

    for (int z = t; z < 1024; z += 512) nh[z] = 0;
    if (w == 0) {
        unsigned vloc[8], pref[8], tot = 0;
#pragma unroll
        for (int c = 0; c < 8; c++) {
            int d = lane * 8 + c;
            unsigned s0 = g_qh[inIdx][b][0][d], s1 = g_qh[inIdx][b][1][d];
            unsigned s2 = g_qh[inIdx][b][2][d], s3 = g_qh[inIdx][b][3][d];
            pref[c] = (q > 0 ? s0 : 0u) + (q > 1 ? s1 : 0u) + (q > 2 ? s2 : 0u);
            unsigned td = s0 + s1 + s2 + s3;
            vloc[c] = tot; tot += td;
        }
        unsigned e = tot;
#pragma unroll
        for (int o = 1; o < 32; o <<= 1) { unsigned y = __shfl_up_sync(FULLW, e, o); if (lane >= o) e += y; }
        e -= tot;
#pragma unroll
        for (int c = 0; c < 8; c++) binbase[lane * 8 + c] = e + vloc[c] + pref[c];
    }
    __syncthreads();

    for (int tt = 0; tt < 4; tt++) {
        int base = i0 + tt * 4096;
        int tn = i1 - base;
        if (tn < 0) tn = 0;
        if (tn > TILE) tn = TILE;

        for (int z = t; z < (256 * 17 + 2) / 2; z += 512) ((unsigned*)whist)[z] = 0;
        __syncthreads();

        unsigned key[8], lr8[8]; int dg[8];
#pragma unroll
        for (int qq = 0; qq < 8; qq++) {
            int idx = base + w * 256 + qq * 32 + lane;
            unsigned d = 256u;
            if (idx < i1) { key[qq] = src[idx]; d = (key[qq] >> shift) & 255u; }
            dg[qq] = (int)d;
            unsigned m = __match_any_sync(FULLW, d);
            unsigned r = __popc(m & ltm);
            int leader = __ffs(m) - 1;
            unsigned old = 0;
            if (r == 0) {
                old = whist[d * 17 + w];
                whist[d * 17 + w] = (unsigned short)(old + __popc(m));
            }
            old = __shfl_sync(m, old, leader);
            lr8[qq] = old + r;
            __syncwarp();
        }
        __syncthreads();

        {   // column scan: warp w owns digits [w*16, w*16+16), 2 digits per step via half-warps
            int sub = lane >> 4;
            int ww  = lane & 15;
#pragma unroll
            for (int qd = 0; qd < 8; qd++) {
                int d = w * 16 + qd * 2 + sub;
                unsigned v = whist[d * 17 + ww];
                unsigned orig = v;
#pragma unroll
                for (int o = 1; o < 16; o <<= 1) {
                    unsigned y = __shfl_up_sync(FULLW, v, o, 16);
                    if (ww >= o) v += y;
                }
                whist[d * 17 + ww] = (unsigned short)(v - orig);
                if (ww == 15) tiletot[d] = v;
            }
        }
        __syncthreads();

        if (w == 0) {
            unsigned vloc[8], tot = 0;
#pragma unroll
            for (int c = 0; c < 8; c++) { unsigned x = tiletot[lane * 8 + c]; vloc[c] = tot; tot += x; }
            unsigned e = tot;
#pragma unroll
            for (int o = 1; o < 32; o <<= 1) { unsigned y = __shfl_up_sync(FULLW, e, o); if (lane >= o) e += y; }
            e -= tot;
#pragma unroll
            for (int c = 0; c < 8; c++) tstart[lane * 8 + c] = e + vloc[c];
        }
        __syncthreads();

#pragma unroll
        for (int qq = 0; qq < 8; qq++) {
            if (dg[qq] < 256) {
                unsigned p = tstart[dg[qq]] + (unsigned)whist[dg[qq] * 17 + w] + lr8[qq];
                skey[p] = key[qq];
            }
        }
        __syncthreads();

        {
            int j0 = t * 8;
            uint4 k0v = *(const uint4*)&skey[j0];
            uint4 k1v = *(const uint4*)&skey[j0 + 4];
            unsigned ks[8] = {k0v.x, k0v.y, k0v.z, k0v.w, k1v.x, k1v.y, k1v.z, k1v.w};
#pragma unroll
            for (int qq = 0; qq < 8; qq++) {
                int j = j0 + qq;
                if (j < tn) {
                    unsigned kq = ks[qq];
                    unsigned d = (kq >> shift) & 255u;
                    unsigned dp = binbase[d] + (unsigned)j - tstart[d];
                    dst[dp] = kq;
                    if (doNext)
                        atomicAdd(&nh[((dp >> 14) << 8) | ((kq >> nextShift) & 255u)], 1u);
                }
            }
        }
        __syncthreads();
        if (t < 256) binbase[t] += tiletot[t];
        __syncthreads();
    }
    if (doNext) {
        for (int z = t; z < 1024; z += 512) {
            unsigned c = nh[z];
            if (c) atomicAdd(&g_qh[outIdx][b][z >> 8][z & 255], c);
        }
    }
}

// ---------------- positives: smem bitonic sort (4096), emit pos_cat ----------------
__global__ __launch_bounds__(512) void k_possort() {
    __shared__ float s[4096];
    int b = blockIdx.x, t = threadIdx.x;
    int n = g_pos_wr[b];
    if (n > POSCAP) n = POSCAP;
    float ninf = __int_as_float(0xff800000);
    for (int i = t; i < 4096; i += 512)
        s[i] = (i < n) ? g_posv[b * POSCAP + i] : ninf;
    __syncthreads();
    for (int kk = 2; kk <= 4096; kk <<= 1) {
        for (int j = kk >> 1; j > 0; j >>= 1) {
            for (int i = t; i < 4096; i += 512) {
                int l = i ^ j;
                if (l > i) {
                    float a = s[i], c = s[l];
                    bool up = ((i & kk) == 0);
                    if (up ? (a > c) : (a < c)) { s[i] = c; s[l] = a; }
                }
            }
            __syncthreads();
        }
    }
    if (t == 0) {
        int tk = g_reps - 1;
        for (int j = 0; j < tk; j++) g_poscat[b * 32 + j] = s[4095 - j];
        g_poscat[b * 32 + tk] = s[4095 - (g_pos_min - 1)];
    }
}

// ---------------- writer: smem-broadcast, 16 segment-CTAs per b-row ----------------
__global__ __launch_bounds__(512) void k_write(float* __restrict__ out) {
    __shared__ __align__(16) float s[4096];
    int b = blockIdx.x >> 4;
    int seg = blockIdx.x & 15;
    int t = threadIdx.x;
    int reps = g_reps, nm = g_neg_min, cnt = g_neg_cnt[b];
    size_t W = (size_t)nm + 1;
    const unsigned* asc = g_keysB + ((size_t)b << 16);
    const float invT = 1.0f / 0.3f;

    if (seg == 0 && t < reps)
        out[(size_t)(b * reps + t) * W] = g_poscat[b * 32 + t] * invT;

    int per = (nm + 15) >> 4;
    int i0 = seg * per;
    int i1 = i0 + per; if (i1 > nm) i1 = nm;

    for (int c0 = i0; c0 < i1; c0 += 4096) {
        int len = i1 - c0; if (len > 4096) len = 4096;
        int glo = cnt - c0 - len;
        for (int u = t; u < len; u += 512)
            s[len - 1 - u] = unflip_f32(asc[glo + u]) * invT;
        __syncthreads();
        for (int j = 0; j < reps; j++) {
            size_t doff = (size_t)(b * reps + j) * W + 1 + c0;
            float* dst = out + doff;
            int head = (int)((4 - (doff & 3)) & 3); if (head > len) head = len;
            for (int u = t; u < head; u += 512) dst[u] = s[u];
            int nb = (len - head) >> 2;
            for (int u = t; u < nb; u += 512) {
                int p = head + u * 4;
                float4 v; v.x = s[p]; v.y = s[p + 1]; v.z = s[p + 2]; v.w = s[p + 3];
                __stcs((float4*)&dst[p], v);
            }
            for (int u = head + nb * 4 + t; u < len; u += 512) dst[u] = s[u];
        }
        __syncthreads();
    }
}

// ---------------- launch ----------------
extern "C" void kernel_launch(void* const* d_in, const int* in_sizes, int n_in,
                              void* d_out, int out_size) {
    const float*    A  = (const float*)d_in[0];
    const float*    Bq = (const float*)d_in[1];
    const unsigned* lq = (const unsigned*)d_in[2];
    const unsigned* lQ = (const unsigned*)d_in[3];
    const int*      tk = (const int*)d_in[4];
    float* out = (float*)d_out;
    (void)in_sizes; (void)n_in; (void)out_size;

    // Order: 4th launch (ncu's captured slot) = k_upass (new unstable pass 1).
    k_gemm<<<K_ / 128, 256>>>(A, Bq);
    k_init0<<<64, 256>>>(lq, lQ);
    k_part<<<B_ * 8, 256>>>();
    k_upass<<<B_ * 4, 512>>>();
    k_count<<<B_, 256>>>();
    k_fin<<<1, 1>>>(tk);
    k_pass<<<B_ * 4, 512>>>(1, 16, 1, 2, 1);
    k_pass<<<B_ * 4, 512>>>(0, 24, 2, 2, 0);
    k_possort<<<B_, 512>>>();
    k_write<<<B_ * 16, 512>>>(out);
}

// round 15
// speedup vs baseline: 1.3105x; 1.0166x over previous
#include <cuda_runtime.h>
#include <cstdint>

#define B_ 128
#define K_ 65536
#define C_ 768
#define POSCAP 4096
#define FULLW 0xffffffffu
#define TILE 4096

// ---------------- device scratch ----------------
static __device__ unsigned g_keysA[(size_t)B_ * K_];
static __device__ unsigned g_keysB[(size_t)B_ * K_];
static __device__ float    g_cos[(size_t)B_ * K_];
static __device__ float    g_posv[B_ * POSCAP];
static __device__ unsigned g_qh[3][B_][8][256];
static __device__ int      g_neg_cnt[B_];
static __device__ int      g_pos_wr[B_];
static __device__ int      g_minpos;
static __device__ int      g_maxpos;
static __device__ int      g_pos_min;
static __device__ int      g_neg_min;
static __device__ int      g_reps;
static __device__ float    g_poscat[B_ * 32];
static __device__ __align__(16) unsigned char g_lab8[K_];
static __device__ unsigned char g_labq8[B_];

__device__ __forceinline__ unsigned flip_f32(float v) {
    unsigned b = __float_as_uint(v);
    return (b & 0x80000000u) ? ~b : (b | 0x80000000u);
}
__device__ __forceinline__ float unflip_f32(unsigned u) {
    unsigned b = (u & 0x80000000u) ? (u & 0x7fffffffu) : ~u;
    return __uint_as_float(b);
}

#define PACK2(dst, lo, hi)  asm("mov.b64 %0, {%1, %2};" : "=l"(dst) : "f"(lo), "f"(hi))
#define UNPACK2(lo, hi, in) asm("mov.b64 {%0, %1}, %2;" : "=f"(lo), "=f"(hi) : "l"(in))
#define FMA2(d, a, b)       asm("fma.rn.f32x2 %0, %1, %2, %0;" : "+l"(d) : "l"(a), "l"(b))

// ---------------- init0: counters + qh zero + label compress ----------------
__global__ __launch_bounds__(256) void k_init0(const unsigned* __restrict__ lq,
                                               const unsigned* __restrict__ lQ) {
    int b = blockIdx.x, t = threadIdx.x;
    unsigned v = 0;
    for (int i = 2 * t + 1; i < 16384; i += 512) v |= lQ[i];
    __shared__ unsigned sh[256];
    sh[t] = v; __syncthreads();
    for (int o = 128; o; o >>= 1) { if (t < o) sh[t] |= sh[t + o]; __syncthreads(); }
    int s = (sh[0] == 0u) ? 2 : 1;

    int i = (b * 256 + t) * 4;
    uchar4 lv;
    lv.x = (unsigned char)lQ[(size_t)(i + 0) * s];
    lv.y = (unsigned char)lQ[(size_t)(i + 1) * s];
    lv.z = (unsigned char)lQ[(size_t)(i + 2) * s];
    lv.w = (unsigned char)lQ[(size_t)(i + 3) * s];
    *(uchar4*)&g_lab8[i] = lv;

    for (int z = b * 256 + t; z < 3 * B_ * 2048; z += 64 * 256)
        ((unsigned*)g_qh)[z] = 0;
    if (b == 0) {
        if (t < B_) {
            g_neg_cnt[t] = 0; g_pos_wr[t] = 0;
            g_labq8[t] = (unsigned char)lq[t * s];
        }
        if (t == 0) { g_minpos = 1 << 30; g_maxpos = 0; }
    }
}

// ---------------- per-row positive counts (u8 labels) ----------------
__global__ void k_count() {
    int b = blockIdx.x, t = threadIdx.x;
    unsigned mx = g_labq8[b] * 0x01010101u;
    int c8 = 0;
    const uint4* L = (const uint4*)g_lab8;
    for (int k = t; k < K_ / 16; k += 256) {
        uint4 w = L[k];
        c8 += __popc(__vcmpeq4(w.x, mx)) + __popc(__vcmpeq4(w.y, mx))
            + __popc(__vcmpeq4(w.z, mx)) + __popc(__vcmpeq4(w.w, mx));
    }
    int c = c8 >> 3;
    __shared__ int sh[256];
    sh[t] = c; __syncthreads();
    for (int o = 128; o; o >>= 1) { if (t < o) sh[t] += sh[t + o]; __syncthreads(); }
    if (t == 0) { atomicMin(&g_minpos, sh[0]); atomicMax(&g_maxpos, sh[0]); }
}

__global__ void k_fin(const int* __restrict__ tkp) {
    int tk = *tkp;
    g_pos_min = g_minpos;
    g_neg_min = K_ - g_maxpos;
    int t = (tk < g_minpos) ? tk : g_minpos;
    g_reps = t + 1;
}

// ---------------- fp32 GEMM (rotated-pair f32x2 FMA, XOR-swizzled smem) ----------------
#define KC 32
__global__ __launch_bounds__(256, 2) void k_gemm(const float* __restrict__ A,
                                                 const float* __restrict__ Bq) {
    __shared__ float As[KC * 128];
    __shared__ float Bs[KC * 128];
    int t  = threadIdx.x;
    int nt = blockIdx.x * 128;
    int tx = t & 15, ty = t >> 4;
    int lr = t >> 3, lk4 = (t & 7) * 4;

    unsigned long long accD[4][4], accX[4][4];
#pragma unroll
    for (int p = 0; p < 4; p++)
#pragma unroll
        for (int j = 0; j < 4; j++) { accD[p][j] = 0ull; accX[p][j] = 0ull; }

    for (int k0 = 0; k0 < C_; k0 += KC) {
#pragma unroll
        for (int it = 0; it < 4; it++) {
            int r = it * 32 + lr;
            int rs = r ^ lk4;
            float4 av = *(const float4*)&A[r * C_ + k0 + lk4];
            float4 bv = *(const float4*)&Bq[(size_t)(nt + r) * C_ + k0 + lk4];
            As[(lk4 + 0) * 128 + rs] = av.x; As[(lk4 + 1) * 128 + rs] = av.y;
            As[(lk4 + 2) * 128 + rs] = av.z; As[(lk4 + 3) * 128 + rs] = av.w;
            Bs[(lk4 + 0) * 128 + rs] = bv.x; Bs[(lk4 + 1) * 128 + rs] = bv.y;
            Bs[(lk4 + 2) * 128 + rs] = bv.z; Bs[(lk4 + 3) * 128 + rs] = bv.w;
        }
        __syncthreads();
#pragma unroll
        for (int k = 0; k < KC; k++) {
            int fa = k & 28;
            const float* arow = &As[k * 128];
            const float* brow = &Bs[k * 128];
            int bA = (ty * 8) ^ fa;
            int bB = (tx * 8) ^ fa;
            float4 a0 = *(const float4*)&arow[bA];
            float4 a1 = *(const float4*)&arow[bA ^ 4];
            float4 b0 = *(const float4*)&brow[bB];
            float4 b1 = *(const float4*)&brow[bB ^ 4];
            unsigned long long ap[4], bp[4], bs[4];
            PACK2(ap[0], a0.x, a0.y); PACK2(ap[1], a0.z, a0.w);
            PACK2(ap[2], a1.x, a1.y); PACK2(ap[3], a1.z, a1.w);
            PACK2(bp[0], b0.x, b0.y); PACK2(bp[1], b0.z, b0.w);
            PACK2(bp[2], b1.x, b1.y); PACK2(bp[3], b1.z, b1.w);
            PACK2(bs[0], b0.y, b0.x); PACK2(bs[1], b0.w, b0.z);
            PACK2(bs[2], b1.y, b1.x); PACK2(bs[3], b1.w, b1.z);
#pragma unroll
            for (int p = 0; p < 4; p++) {
                FMA2(accD[p][0], ap[p], bp[0]); FMA2(accX[p][0], ap[p], bs[0]);
                FMA2(accD[p][1], ap[p], bp[1]); FMA2(accX[p][1], ap[p], bs[1]);
                FMA2(accD[p][2], ap[p], bp[2]); FMA2(accX[p][2], ap[p], bs[2]);
                FMA2(accD[p][3], ap[p], bp[3]); FMA2(accX[p][3], ap[p], bs[3]);
            }
        }
        __syncthreads();
    }
#pragma unroll
    for (int p = 0; p < 4; p++) {
        float* de = &g_cos[(size_t)(ty * 8 + 2 * p) * K_ + nt + tx * 8];
        float* dо = &g_cos[(size_t)(ty * 8 + 2 * p + 1) * K_ + nt + tx * 8];
#pragma unroll
        for (int j = 0; j < 4; j++) {
            float dl, dh, xl, xh;
            UNPACK2(dl, dh, accD[p][j]);
            UNPACK2(xl, xh, accX[p][j]);
            *(float2*)&de[2 * j] = make_float2(dl, xl);
            *(float2*)&dо[2 * j] = make_float2(xh, dh);
        }
    }
}

// ---------------- partition (4 elems/thread, u8 labels) + pass-1 eighth hist ----------------
__global__ __launch_bounds__(256) void k_part() {
    __shared__ unsigned qh[2048];   // [eighth][digit] for pass-1 (bits 8-16)
    int row = blockIdx.x >> 3;
    int chunk = blockIdx.x & 7;
    int t = threadIdx.x, lane = t & 31;
    unsigned ltm = (1u << lane) - 1u;
    unsigned mylx4 = g_labq8[row] * 0x01010101u;
    for (int z = t; z < 2048; z += 256) qh[z] = 0;
    __syncthreads();
    const float4* cosr = (const float4*)(g_cos + (size_t)row * K_) + chunk * 2048;
    const unsigned* lab4 = (const unsigned*)g_lab8 + chunk * 2048;
    unsigned* keys = g_keysA + ((size_t)row << 16);

    for (int it = 0; it < 8; it++) {
        float4 v = cosr[it * 256 + t];
        unsigned lb = lab4[it * 256 + t];
        unsigned eq = __vcmpeq4(lb, mylx4);
        unsigned m[4];
        m[0] = __ballot_sync(FULLW, (eq & 0x000000FFu) == 0);
        m[1] = __ballot_sync(FULLW, (eq & 0x0000FF00u) == 0);
        m[2] = __ballot_sync(FULLW, (eq & 0x00FF0000u) == 0);
        m[3] = __ballot_sync(FULLW, (eq & 0xFF000000u) == 0);
        int c0 = __popc(m[0]), c1 = __popc(m[1]), c2 = __popc(m[2]), c3 = __popc(m[3]);
        int tot = c0 + c1 + c2 + c3;
        int nbase = 0, pbase = 0;
        if (lane == 0) {
            if (tot) nbase = atomicAdd(&g_neg_cnt[row], tot);
            if (tot < 128) pbase = atomicAdd(&g_pos_wr[row], 128 - tot);
        }
        nbase = __shfl_sync(FULLW, nbase, 0);
        pbase = __shfl_sync(FULLW, pbase, 0);
        int npre[4] = {0, c0, c0 + c1, c0 + c1 + c2};
        float vals[4] = {v.x, v.y, v.z, v.w};
#pragma unroll
        for (int e = 0; e < 4; e++) {
            bool neg = (m[e] >> lane) & 1;
            if (neg) {
                int idx = nbase + npre[e] + __popc(m[e] & ltm);
                unsigned u = flip_f32(vals[e]);
                keys[idx] = u;
                atomicAdd(&qh[((idx >> 13) << 8) | ((u >> 8) & 255u)], 1u);
            } else {
                int pidx = pbase + (32 * e - npre[e]) + __popc(~m[e] & ltm);
                if (pidx < POSCAP) g_posv[row * POSCAP + pidx] = vals[e];
            }
        }
    }
    __syncthreads();
    for (int z = t; z < 2048; z += 256) {
        unsigned c = qh[z];
        if (c) atomicAdd(&((unsigned*)g_qh[0][row])[z], c);
    }
}

// ---------------- segment base helper: per-digit global base for segment q ----------------
__device__ __forceinline__ void seg_base(unsigned* outbase, int idxH, int b, int q,
                                         int lane) {
    unsigned vloc[8], pref[8], tot = 0;
#pragma unroll
    for (int c = 0; c < 8; c++) {
        int d = lane * 8 + c;
        unsigned td = 0, pf = 0;
#pragma unroll
        for (int ss = 0; ss < 8; ss++) {
            unsigned x = g_qh[idxH][b][ss][d];
            td += x;
            if (ss < q) pf += x;
        }
        pref[c] = pf;
        vloc[c] = tot; tot += td;
    }
    unsigned e = tot;
#pragma unroll
    for (int o = 1; o < 32; o <<= 1) { unsigned y = __shfl_up_sync(FULLW, e, o); if (lane >= o) e += y; }
    e -= tot;
#pragma unroll
    for (int c = 0; c < 8; c++) outbase[lane * 8 + c] = e + vloc[c] + pref[c];
}

// ---------------- pass 1 (UNSTABLE): warp-aggregated atomic scatter, bits [8:16) ----------------
__global__ __launch_bounds__(512) void k_upass() {
    int b = blockIdx.x >> 3, q = blockIdx.x & 7;
    int t = threadIdx.x, lane = t & 31, w = t >> 5;
    unsigned ltm = (1u << lane) - 1u;
    int n = g_neg_cnt[b];
    const unsigned* src = g_keysA + ((size_t)b << 16);
    unsigned*       dst = g_keysB + ((size_t)b << 16);
    int i0 = q << 13, i1 = i0 + 8192;
    if (i1 > n) i1 = n;
    if (i1 < i0) i1 = i0;

    __shared__ unsigned abase[256];
    __shared__ unsigned nh[2048];

    for (int z = t; z < 2048; z += 512) nh[z] = 0;
    if (w == 0) seg_base(abase, 0, b, q, lane);
    __syncthreads();

    for (int sweep = 0; sweep < 2; sweep++) {
        int base = i0 + sweep * 4096 + t * 8;
        uint4 k0v = *(const uint4*)&src[base];
        uint4 k1v = *(const uint4*)&src[base + 4];
        unsigned ks[8] = {k0v.x, k0v.y, k0v.z, k0v.w, k1v.x, k1v.y, k1v.z, k1v.w};
#pragma unroll
        for (int qq = 0; qq < 8; qq++) {
            int idx = base + qq;
            unsigned d = (idx < i1) ? ((ks[qq] >> 8) & 255u) : 256u;
            unsigned m = __match_any_sync(FULLW, d);
            unsigned r = __popc(m & ltm);
            int leader = __ffs(m) - 1;
            unsigned old = 0;
            if (d < 256u && r == 0) old = atomicAdd(&abase[d], __popc(m));
            old = __shfl_sync(m, old, leader);
            if (d < 256u) {
                unsigned dp = old + r;
                dst[dp] = ks[qq];
                atomicAdd(&nh[((dp >> 13) << 8) | ((ks[qq] >> 16) & 255u)], 1u);
            }
        }
    }
    __syncthreads();
    for (int z = t; z < 2048; z += 512) {
        unsigned c = nh[z];
        if (c) atomicAdd(&((unsigned*)g_qh[1][b])[z], c);
    }
}

// ---------------- stable radix pass: 512 thr x 8 keys, CTA = (row, eighth), 2 tiles ----------------
__global__ __launch_bounds__(512, 2) void k_pass(int srcSel, int shift, int inIdx,
                                                 int outIdx, int doNext) {
    int b = blockIdx.x >> 3, q = blockIdx.x & 7;
    int t = threadIdx.x, lane = t & 31, w = t >> 5;
    unsigned ltm = (1u << lane) - 1u;
    int n = g_neg_cnt[b];
    const unsigned* src = (srcSel ? g_keysB : g_keysA) + ((size_t)b << 16);
    unsigned*       dst = (srcSel ? g_keysA : g_keysB) + ((size_t)b << 16);
    int i0 = q << 13, i1 = i0 + 8192;
    if (i1 > n) i1 = n;
    if (i1 < i0) i1 = i0;
    int nextShift = shift + 8;

    __shared__ unsigned binbase[256];
    __shared__ unsigned tstart[256];
    __shared__ unsigned tiletot[256];
    __shared__ unsigned nh[2048];
    __shared__ __align__(16) unsigned short whist[256 * 17 + 2];
    __shared__ __align__(16) unsigned skey[TILE];

    for (int z = t; z < 2048; z += 512) nh[z] = 0;
    if (w == 0) seg_base(binbase, inIdx, b, q, lane);
    __syncthreads();

    for (int tt = 0; tt < 2; tt++) {
        int base = i0 + tt * 4096;
        int tn = i1 - base;
        if (tn < 0) tn = 0;
        if (tn > TILE) tn = TILE;

        for (int z = t; z < (256 * 17 + 2) / 2; z += 512) ((unsigned*)whist)[z] = 0;
        __syncthreads();

        unsigned key[8], lr8[8]; int dg[8];
#pragma unroll
        for (int qq = 0; qq < 8; qq++) {
            int idx = base + w * 256 + qq * 32 + lane;
            unsigned d = 256u;
            if (idx < i1) { key[qq] = src[idx]; d = (key[qq] >> shift) & 255u; }
            dg[qq] = (int)d;
            unsigned m = __match_any_sync(FULLW, d);
            unsigned r = __popc(m & ltm);
            int leader = __ffs(m) - 1;
            unsigned old = 0;
            if (r == 0) {
                old = whist[d * 17 + w];
                whist[d * 17 + w] = (unsigned short)(old + __popc(m));
            }
            old = __shfl_sync(m, old, leader);
            lr8[qq] = old + r;
            __syncwarp();
        }
        __syncthreads();

        {   // column scan: warp w owns digits [w*16, w*16+16)
            int sub = lane >> 4;
            int ww  = lane & 15;
#pragma unroll
            for (int qd = 0; qd < 8; qd++) {
                int d = w * 16 + qd * 2 + sub;
                unsigned v = whist[d * 17 + ww];
                unsigned orig = v;
#pragma unroll
                for (int o = 1; o < 16; o <<= 1) {
                    unsigned y = __shfl_up_sync(FULLW, v, o, 16);
                    if (ww >= o) v += y;
                }
                whist[d * 17 + ww] = (unsigned short)(v - orig);
                if (ww == 15) tiletot[d] = v;
            }
        }
        __syncthreads();

        if (w == 0) {
            unsigned vloc[8], tot = 0;
#pragma unroll
            for (int c = 0; c < 8; c++) { unsigned x = tiletot[lane * 8 + c]; vloc[c] = tot; tot += x; }
            unsigned e = tot;
#pragma unroll
            for (int o = 1; o < 32; o <<= 1) { unsigned y = __shfl_up_sync(FULLW, e, o); if (lane >= o) e += y; }
            e -= tot;
#pragma unroll
            for (int c = 0; c < 8; c++) tstart[lane * 8 + c] = e + vloc[c];
        }
        __syncthreads();

#pragma unroll
        for (int qq = 0; qq < 8; qq++) {
            if (dg[qq] < 256) {
                unsigned p = tstart[dg[qq]] + (unsigned)whist[dg[qq] * 17 + w] + lr8[qq];
                skey[p] = key[qq];
            }
        }
        __syncthreads();

        {
            int j0 = t * 8;
            uint4 k0v = *(const uint4*)&skey[j0];
            uint4 k1v = *(const uint4*)&skey[j0 + 4];
            unsigned ks[8] = {k0v.x, k0v.y, k0v.z, k0v.w, k1v.x, k1v.y, k1v.z, k1v.w};
#pragma unroll
            for (int qq = 0; qq < 8; qq++) {
                int j = j0 + qq;
                if (j < tn) {
                    unsigned kq = ks[qq];
                    unsigned d = (kq >> shift) & 255u;
                    unsigned dp = binbase[d] + (unsigned)j - tstart[d];
                    dst[dp] = kq;
                    if (doNext)
                        atomicAdd(&nh[((dp >> 13) << 8) | ((kq >> nextShift) & 255u)], 1u);
                }
            }
        }
        __syncthreads();
        if (t < 256) binbase[t] += tiletot[t];
        __syncthreads();
    }
    if (doNext) {
        for (int z = t; z < 2048; z += 512) {
            unsigned c = nh[z];
            if (c) atomicAdd(&((unsigned*)g_qh[outIdx][b])[z], c);
        }
    }
}

// ---------------- positives: smem bitonic sort (4096), emit pos_cat ----------------
__global__ __launch_bounds__(512) void k_possort() {
    __shared__ float s[4096];
    int b = blockIdx.x, t = threadIdx.x;
    int n = g_pos_wr[b];
    if (n > POSCAP) n = POSCAP;
    float ninf = __int_as_float(0xff800000);
    for (int i = t; i < 4096; i += 512)
        s[i] = (i < n) ? g_posv[b * POSCAP + i] : ninf;
    __syncthreads();
    for (int kk = 2; kk <= 4096; kk <<= 1) {
        for (int j = kk >> 1; j > 0; j >>= 1) {
            for (int i = t; i < 4096; i += 512) {
                int l = i ^ j;
                if (l > i) {
                    float a = s[i], c = s[l];
                    bool up = ((i & kk) == 0);
                    if (up ? (a > c) : (a < c)) { s[i] = c; s[l] = a; }
                }
            }
            __syncthreads();
        }
    }
    if (t == 0) {
        int tk = g_reps - 1;
        for (int j = 0; j < tk; j++) g_poscat[b * 32 + j] = s[4095 - j];
        g_poscat[b * 32 + tk] = s[4095 - (g_pos_min - 1)];
    }
}

// ---------------- writer: smem-broadcast, 16 segment-CTAs per b-row ----------------
__global__ __launch_bounds__(512) void k_write(float* __restrict__ out) {
    __shared__ __align__(16) float s[4096];
    int b = blockIdx.x >> 4;
    int seg = blockIdx.x & 15;
    int t = threadIdx.x;
    int reps = g_reps, nm = g_neg_min, cnt = g_neg_cnt[b];
    size_t W = (size_t)nm + 1;
    const unsigned* asc = g_keysB + ((size_t)b << 16);
    const float invT = 1.0f / 0.3f;

    if (seg == 0 && t < reps)
        out[(size_t)(b * reps + t) * W] = g_poscat[b * 32 + t] * invT;

    int per = (nm + 15) >> 4;
    int i0 = seg * per;
    int i1 = i0 + per; if (i1 > nm) i1 = nm;

    for (int c0 = i0; c0 < i1; c0 += 4096) {
        int len = i1 - c0; if (len > 4096) len = 4096;
        int glo = cnt - c0 - len;
        for (int u = t; u < len; u += 512)
            s[len - 1 - u] = unflip_f32(asc[glo + u]) * invT;
        __syncthreads();
        for (int j = 0; j < reps; j++) {
            size_t doff = (size_t)(b * reps + j) * W + 1 + c0;
            float* dst = out + doff;
            int head = (int)((4 - (doff & 3)) & 3); if (head > len) head = len;
            for (int u = t; u < head; u += 512) dst[u] = s[u];
            int nb = (len - head) >> 2;
            for (int u = t; u < nb; u += 512) {
                int p = head + u * 4;
                float4 v; v.x = s[p]; v.y = s[p + 1]; v.z = s[p + 2]; v.w = s[p + 3];
                __stcs((float4*)&dst[p], v);
            }
            for (int u = head + nb * 4 + t; u < len; u += 512) dst[u] = s[u];
        }
        __syncthreads();
    }
}

// ---------------- launch ----------------
extern "C" void kernel_launch(void* const* d_in, const int* in_sizes, int n_in,
                              void* d_out, int out_size) {
    const float*    A  = (const float*)d_in[0];
    const float*    Bq = (const float*)d_in[1];
    const unsigned* lq = (const unsigned*)d_in[2];
    const unsigned* lQ = (const unsigned*)d_in[3];
    const int*      tk = (const int*)d_in[4];
    float* out = (float*)d_out;
    (void)in_sizes; (void)n_in; (void)out_size;

    // Order: 4th launch (ncu's captured slot) = k_gemm (verify rotated-pair).
    k_init0<<<64, 256>>>(lq, lQ);
    k_count<<<B_, 256>>>();
    k_fin<<<1, 1>>>(tk);
    k_gemm<<<K_ / 128, 256>>>(A, Bq);
    k_part<<<B_ * 8, 256>>>();
    k_upass<<<B_ * 8, 512>>>();
    k_pass<<<B_ * 8, 512>>>(1, 16, 1, 2, 1);
    k_pass<<<B_ * 8, 512>>>(0, 24, 2, 2, 0);
    k_possort<<<B_, 512>>>();
    k_write<<<B_ * 16, 512>>>(out);
}